// round 5
// baseline (speedup 1.0000x reference)
#include <cuda_runtime.h>
#include <cstdint>

// Problem constants
#define Bq 2
#define Tq 2048
#define Dq 1024
#define VDq 2048
#define FFq 2752
#define Hq 16
#define DKq 64
#define DVq 128
#define Mq (Bq*Tq)   // 4096 rows

// ---------------- scratch (device globals; no allocation allowed) ----------
__device__ float g_h [Mq*(size_t)Dq];
__device__ float g_qp[Mq*(size_t)Dq];
__device__ float g_kp[Mq*(size_t)Dq];
__device__ float g_vp[Mq*(size_t)VDq];
__device__ float g_q [Mq*(size_t)Dq];
__device__ float g_k [Mq*(size_t)Dq];
__device__ float g_v [Mq*(size_t)VDq];
__device__ float g_gt[Mq*(size_t)VDq];
__device__ float g_bt[Mq*(size_t)Hq];
__device__ float g_gd[Mq*(size_t)Hq];
__device__ float g_o [Mq*(size_t)VDq];
__device__ float g_x [Mq*(size_t)Dq];
__device__ float g_h2[Mq*(size_t)Dq];
__device__ float g_gb[Mq*(size_t)FFq];
__device__ float g_ub[Mq*(size_t)FFq];

// ---------------- helpers ---------------------------------------------------
__device__ __forceinline__ float siluf(float x) {
    return x / (1.0f + __expf(-x));
}

__device__ __forceinline__ unsigned long long ffma2(unsigned long long a,
                                                    unsigned long long b,
                                                    unsigned long long c) {
    unsigned long long d;
    asm("fma.rn.f32x2 %0, %1, %2, %3;" : "=l"(d) : "l"(a), "l"(b), "l"(c));
    return d;
}
__device__ __forceinline__ unsigned long long dup2(float x) {
    unsigned long long r;
    asm("mov.b64 %0, {%1, %1};" : "=l"(r) : "f"(x));
    return r;
}

// ---------------- RMSNorm over D=1024, one block per row --------------------
__global__ void rmsnorm_kernel(const float* __restrict__ x,
                               const float* __restrict__ w,
                               float* __restrict__ out) {
    int row = blockIdx.x;
    const float4* xr = (const float4*)(x + (size_t)row * Dq);
    float4 v = xr[threadIdx.x];
    float ss = v.x*v.x + v.y*v.y + v.z*v.z + v.w*v.w;
    #pragma unroll
    for (int o = 16; o; o >>= 1) ss += __shfl_xor_sync(0xffffffffu, ss, o);
    __shared__ float red[8];
    int wid = threadIdx.x >> 5, lane = threadIdx.x & 31;
    if (lane == 0) red[wid] = ss;
    __syncthreads();
    float tot = red[0]+red[1]+red[2]+red[3]+red[4]+red[5]+red[6]+red[7];
    float r = rsqrtf(tot * (1.0f / Dq) + 1e-6f);
    float4 wv = ((const float4*)w)[threadIdx.x];
    float4 ov = make_float4(v.x*r*wv.x, v.y*r*wv.y, v.z*r*wv.z, v.w*r*wv.w);
    ((float4*)(out + (size_t)row * Dq))[threadIdx.x] = ov;
}

// ---------------- causal depthwise conv (K=4) + silu -------------------------
__global__ void conv_silu_kernel(const float* __restrict__ in,
                                 const float* __restrict__ w,
                                 float* __restrict__ out, int C) {
    size_t idx = (size_t)blockIdx.x * blockDim.x + threadIdx.x;
    size_t total = (size_t)Mq * C;
    if (idx >= total) return;
    int c = (int)(idx % C);
    size_t bt = idx / C;
    int t = (int)(bt % Tq);
    float4 wv = ((const float4*)w)[c];               // w[c,0..3]
    float acc = wv.w * in[idx];                       // i=3 -> x[t]
    if (t >= 1) acc += wv.z * in[idx - (size_t)C];
    if (t >= 2) acc += wv.y * in[idx - 2*(size_t)C];
    if (t >= 3) acc += wv.x * in[idx - 3*(size_t)C];
    out[idx] = siluf(acc);
}

// ---------------- L2 norm over DK=64 vectors (in place), warp per vector ----
__global__ void l2norm_kernel(float* __restrict__ p) {
    int vec = blockIdx.x * 8 + (threadIdx.x >> 5);
    int lane = threadIdx.x & 31;
    float2* vp = (float2*)(p + (size_t)vec * DKq);
    float2 v = vp[lane];
    float ss = v.x*v.x + v.y*v.y;
    #pragma unroll
    for (int o = 16; o; o >>= 1) ss += __shfl_xor_sync(0xffffffffu, ss, o);
    float r = rsqrtf(ss + 1e-6f);
    vp[lane] = make_float2(v.x * r, v.y * r);
}

// ---------------- beta / g decay (skinny N=16 projections) -------------------
__global__ void ba_kernel(const float* __restrict__ h,
                          const float* __restrict__ b_w,
                          const float* __restrict__ a_w,
                          const float* __restrict__ A_log,
                          const float* __restrict__ dt_bias,
                          float* __restrict__ beta,
                          float* __restrict__ gd) {
    int row = blockIdx.x * 4 + (threadIdx.x >> 5);
    int lane = threadIdx.x & 31;
    int c = lane & 15;
    const float* W = (lane < 16) ? b_w : a_w;
    const float* hr = h + (size_t)row * Dq;
    float a0 = 0.f, a1 = 0.f, a2 = 0.f, a3 = 0.f;
    for (int kk = 0; kk < Dq; kk += 4) {
        a0 += hr[kk+0] * W[(kk+0)*Hq + c];
        a1 += hr[kk+1] * W[(kk+1)*Hq + c];
        a2 += hr[kk+2] * W[(kk+2)*Hq + c];
        a3 += hr[kk+3] * W[(kk+3)*Hq + c];
    }
    float acc = (a0 + a1) + (a2 + a3);
    if (lane < 16) {
        beta[(size_t)row * Hq + c] = 1.0f / (1.0f + __expf(-acc));
    } else {
        float xv = acc + dt_bias[c];
        float sp = fmaxf(xv, 0.f) + log1pf(__expf(-fabsf(xv)));  // stable softplus
        gd[(size_t)row * Hq + c] = -__expf(A_log[c]) * sp;
    }
}

// ---------------- gated delta-rule scan --------------------------------------
// grid = B*H*2 CTAs (each CTA owns half of DV); 256 threads.
// thread: col = half*64 + (tid>>2); owns 16 state rows (sub = tid&3).
__global__ void __launch_bounds__(256)
scan_kernel(const float* __restrict__ q, const float* __restrict__ k,
            const float* __restrict__ v, const float* __restrict__ gd,
            const float* __restrict__ bt, float* __restrict__ o) {
    int half = blockIdx.x & 1;
    int bh = blockIdx.x >> 1;
    int b = bh >> 4, h = bh & 15;
    int tid = threadIdx.x;
    int colL = tid >> 2;
    int sub = tid & 3;
    int col = half * 64 + colL;

    __shared__ float ks[2][64];
    __shared__ float qs[2][64];
    __shared__ float sc[2][2];   // [buf][0]=g, [buf][1]=beta

    size_t baseQK = ((size_t)(b * Tq) * Hq + h) * DKq;      // + t*Hq*DKq
    size_t baseV  = ((size_t)(b * Tq) * Hq + h) * DVq + col; // + t*Hq*DVq
    size_t baseS  = (size_t)(b * Tq) * Hq + h;               // + t*Hq

    float S[16];
    #pragma unroll
    for (int j = 0; j < 16; j++) S[j] = 0.f;

    bool isK = (tid < 64);
    bool isQ = (tid >= 64 && tid < 128);
    bool isS = (tid == 128 || tid == 129);
    int li = tid & 63;
    int si = tid - 128;

    // depth-2 prefetch registers
    float rk0 = 0.f, rk1 = 0.f, rq0 = 0.f, rq1 = 0.f, rs0 = 0.f, rs1 = 0.f;
    float rv0, rv1;

    // prologue: smem buf0 <- t=0, regs <- t=1, t=2
    if (isK) {
        ks[0][li] = k[baseQK + li];
        rk0 = k[baseQK + (size_t)1 * Hq * DKq + li];
        rk1 = k[baseQK + (size_t)2 * Hq * DKq + li];
    }
    if (isQ) {
        qs[0][li] = q[baseQK + li] * 0.125f;
        rq0 = q[baseQK + (size_t)1 * Hq * DKq + li] * 0.125f;
        rq1 = q[baseQK + (size_t)2 * Hq * DKq + li] * 0.125f;
    }
    if (isS) {
        const float* sp = (si == 0) ? gd : bt;
        sc[0][si] = sp[baseS];
        rs0 = sp[baseS + (size_t)1 * Hq];
        rs1 = sp[baseS + (size_t)2 * Hq];
    }
    rv0 = v[baseV];
    rv1 = v[baseV + (size_t)1 * Hq * DVq];
    __syncthreads();

    for (int t = 0; t < Tq; t++) {
        int cur = t & 1, nxt = cur ^ 1;
        // stage t+1 into other buffer; refill depth-2 regs with t+3
        if (t + 1 < Tq) {
            if (isK) {
                ks[nxt][li] = rk0; rk0 = rk1;
                rk1 = (t + 3 < Tq) ? k[baseQK + (size_t)(t + 3) * Hq * DKq + li] : 0.f;
            }
            if (isQ) {
                qs[nxt][li] = rq0; rq0 = rq1;
                rq1 = (t + 3 < Tq) ? q[baseQK + (size_t)(t + 3) * Hq * DKq + li] * 0.125f : 0.f;
            }
            if (isS) {
                sc[nxt][si] = rs0; rs0 = rs1;
                if (t + 3 < Tq) {
                    const float* sp = (si == 0) ? gd : bt;
                    rs1 = sp[baseS + (size_t)(t + 3) * Hq];
                } else rs1 = 0.f;
            }
        }
        float vt = rv0; rv0 = rv1;
        rv1 = (t + 2 < Tq) ? v[baseV + (size_t)(t + 2) * Hq * DVq] : 0.f;

        float gde = sc[cur][0], bet = sc[cur][1];
        float decay = __expf(gde);
        const float* kk = &ks[cur][sub * 16];
        const float* qq = &qs[cur][sub * 16];

        float vp0 = 0.f, vp1 = 0.f;
        #pragma unroll
        for (int j = 0; j < 16; j += 2) {
            S[j]   *= decay; vp0 += kk[j]   * S[j];
            S[j+1] *= decay; vp1 += kk[j+1] * S[j+1];
        }
        float vp = vp0 + vp1;
        vp += __shfl_xor_sync(0xffffffffu, vp, 1);
        vp += __shfl_xor_sync(0xffffffffu, vp, 2);
        float u = bet * (vt - vp);

        float ot0 = 0.f, ot1 = 0.f;
        #pragma unroll
        for (int j = 0; j < 16; j += 2) {
            S[j]   += kk[j]   * u; ot0 += qq[j]   * S[j];
            S[j+1] += kk[j+1] * u; ot1 += qq[j+1] * S[j+1];
        }
        float ot = ot0 + ot1;
        ot += __shfl_xor_sync(0xffffffffu, ot, 1);
        ot += __shfl_xor_sync(0xffffffffu, ot, 2);
        if (sub == 0) o[baseV + (size_t)t * Hq * DVq] = ot;
        __syncthreads();
    }
}

// ---------------- gated per-head RMSNorm: o = rms(o)*w * silu(gate) ---------
__global__ void gated_rmsnorm_kernel(float* __restrict__ o,
                                     const float* __restrict__ w,
                                     const float* __restrict__ gate) {
    int vec = blockIdx.x * 8 + (threadIdx.x >> 5);
    int lane = threadIdx.x & 31;
    float4* op = (float4*)(o + (size_t)vec * DVq);
    const float4* gp = (const float4*)(gate + (size_t)vec * DVq);
    float4 v = op[lane];
    float ss = v.x*v.x + v.y*v.y + v.z*v.z + v.w*v.w;
    #pragma unroll
    for (int off = 16; off; off >>= 1) ss += __shfl_xor_sync(0xffffffffu, ss, off);
    float r = rsqrtf(ss * (1.0f / DVq) + 1e-6f);
    float4 wv = ((const float4*)w)[lane];
    float4 g = gp[lane];
    float4 out;
    out.x = v.x * r * wv.x * siluf(g.x);
    out.y = v.y * r * wv.y * siluf(g.y);
    out.z = v.z * r * wv.z * siluf(g.z);
    out.w = v.w * r * wv.w * siluf(g.w);
    op[lane] = out;
}

// ---------------- SwiGLU activation: gb = silu(gb) * ub ---------------------
__global__ void act_kernel(float* __restrict__ gb, const float* __restrict__ ub) {
    size_t i = (size_t)blockIdx.x * 256 + threadIdx.x;
    if (i >= (size_t)Mq * FFq / 4) return;
    float4 g = ((float4*)gb)[i];
    float4 u = ((const float4*)ub)[i];
    g.x = siluf(g.x) * u.x;
    g.y = siluf(g.y) * u.y;
    g.z = siluf(g.z) * u.z;
    g.w = siluf(g.w) * u.w;
    ((float4*)gb)[i] = g;
}

// ---------------- fp32 GEMM with packed f32x2 FMA ---------------------------
// C[M,N] = A[M,K] @ B[K,N] (+ R), row-major. M=4096, K%16==0, N%4==0.
// 128x128 tile, BK=16, 256 threads, 8x8 per thread, double-buffered smem.
__global__ void __launch_bounds__(256)
gemm_kernel(const float* __restrict__ A, const float* __restrict__ B,
            const float* __restrict__ R, float* __restrict__ C,
            int N, int K, int addR) {
    __shared__ float As[2][16][128];
    __shared__ float Bs[2][16][128];
    const int tid = threadIdx.x;
    const int bm = blockIdx.y * 128;
    const int bn = blockIdx.x * 128;

    const int arow = tid >> 2;          // 0..63 (+64)
    const int acol = (tid & 3) << 2;    // 0,4,8,12
    const int brow = tid >> 5;          // 0..7 (+8)
    const int bcol = (tid & 31) << 2;   // 0..124
    const int tm = (tid >> 4) << 3;
    const int tn = (tid & 15) << 3;

    unsigned long long acc[8][4];
    #pragma unroll
    for (int i = 0; i < 8; i++)
        #pragma unroll
        for (int j = 0; j < 4; j++) acc[i][j] = 0ull;

    auto loadTiles = [&](int buf, int k0) {
        #pragma unroll
        for (int i = 0; i < 2; i++) {
            int r = arow + i * 64;
            float4 va = *(const float4*)(A + (size_t)(bm + r) * K + (k0 + acol));
            As[buf][acol + 0][r] = va.x;
            As[buf][acol + 1][r] = va.y;
            As[buf][acol + 2][r] = va.z;
            As[buf][acol + 3][r] = va.w;
        }
        #pragma unroll
        for (int i = 0; i < 2; i++) {
            int r = brow + i * 8;
            int colg = bn + bcol;
            float4 vb = (colg < N)
                      ? *(const float4*)(B + (size_t)(k0 + r) * N + colg)
                      : make_float4(0.f, 0.f, 0.f, 0.f);
            *(float4*)&Bs[buf][r][bcol] = vb;
        }
    };

    int nk = K >> 4;
    loadTiles(0, 0);
    __syncthreads();
    for (int kt = 0; kt < nk; kt++) {
        int buf = kt & 1;
        if (kt + 1 < nk) loadTiles(buf ^ 1, (kt + 1) << 4);
        #pragma unroll
        for (int k = 0; k < 16; k++) {
            unsigned long long bfr[4];
            const unsigned long long* bp =
                (const unsigned long long*)&Bs[buf][k][tn];
            #pragma unroll
            for (int j = 0; j < 4; j++) bfr[j] = bp[j];
            float4 a0 = *(const float4*)&As[buf][k][tm];
            float4 a1 = *(const float4*)&As[buf][k][tm + 4];
            unsigned long long ad[8];
            ad[0] = dup2(a0.x); ad[1] = dup2(a0.y);
            ad[2] = dup2(a0.z); ad[3] = dup2(a0.w);
            ad[4] = dup2(a1.x); ad[5] = dup2(a1.y);
            ad[6] = dup2(a1.z); ad[7] = dup2(a1.w);
            #pragma unroll
            for (int i = 0; i < 8; i++)
                #pragma unroll
                for (int j = 0; j < 4; j++)
                    acc[i][j] = ffma2(ad[i], bfr[j], acc[i][j]);
        }
        __syncthreads();
    }

    #pragma unroll
    for (int i = 0; i < 8; i++) {
        int row = bm + tm + i;
        #pragma unroll
        for (int j = 0; j < 4; j += 2) {
            int colg = bn + tn + j * 2;
            if (colg < N) {
                float4 ov;
                asm("mov.b64 {%0,%1}, %2;" : "=f"(ov.x), "=f"(ov.y) : "l"(acc[i][j]));
                asm("mov.b64 {%0,%1}, %2;" : "=f"(ov.z), "=f"(ov.w) : "l"(acc[i][j+1]));
                if (addR) {
                    float4 rv = *(const float4*)(R + (size_t)row * N + colg);
                    ov.x += rv.x; ov.y += rv.y; ov.z += rv.z; ov.w += rv.w;
                }
                *(float4*)(C + (size_t)row * N + colg) = ov;
            }
        }
    }
}

// ---------------- host orchestration ----------------------------------------
static inline void launch_gemm(const float* A, const float* B, const float* R,
                               float* C, int N, int K, int addR) {
    dim3 grid((N + 127) / 128, Mq / 128);
    gemm_kernel<<<grid, 256>>>(A, B, R, C, N, K, addR);
}

extern "C" void kernel_launch(void* const* d_in, const int* in_sizes, int n_in,
                              void* d_out, int out_size) {
    const float* hidden     = (const float*)d_in[0];
    const float* norm_w     = (const float*)d_in[1];
    const float* q_w        = (const float*)d_in[2];
    const float* k_w        = (const float*)d_in[3];
    const float* v_w        = (const float*)d_in[4];
    const float* b_w        = (const float*)d_in[5];
    const float* a_w        = (const float*)d_in[6];
    const float* A_log      = (const float*)d_in[7];
    const float* dt_bias    = (const float*)d_in[8];
    const float* conv_q_w   = (const float*)d_in[9];
    const float* conv_k_w   = (const float*)d_in[10];
    const float* conv_v_w   = (const float*)d_in[11];
    const float* g_w        = (const float*)d_in[12];
    const float* o_norm_w   = (const float*)d_in[13];
    const float* o_w        = (const float*)d_in[14];
    const float* post_norm_w= (const float*)d_in[15];
    const float* gate_w     = (const float*)d_in[16];
    const float* up_w       = (const float*)d_in[17];
    const float* down_w     = (const float*)d_in[18];
    float* out = (float*)d_out;

    float *p_h, *p_qp, *p_kp, *p_vp, *p_q, *p_k, *p_v, *p_gt, *p_bt, *p_gd,
          *p_o, *p_x, *p_h2, *p_gb, *p_ub;
    cudaGetSymbolAddress((void**)&p_h,  g_h);
    cudaGetSymbolAddress((void**)&p_qp, g_qp);
    cudaGetSymbolAddress((void**)&p_kp, g_kp);
    cudaGetSymbolAddress((void**)&p_vp, g_vp);
    cudaGetSymbolAddress((void**)&p_q,  g_q);
    cudaGetSymbolAddress((void**)&p_k,  g_k);
    cudaGetSymbolAddress((void**)&p_v,  g_v);
    cudaGetSymbolAddress((void**)&p_gt, g_gt);
    cudaGetSymbolAddress((void**)&p_bt, g_bt);
    cudaGetSymbolAddress((void**)&p_gd, g_gd);
    cudaGetSymbolAddress((void**)&p_o,  g_o);
    cudaGetSymbolAddress((void**)&p_x,  g_x);
    cudaGetSymbolAddress((void**)&p_h2, g_h2);
    cudaGetSymbolAddress((void**)&p_gb, g_gb);
    cudaGetSymbolAddress((void**)&p_ub, g_ub);

    // 1) pre-norm
    rmsnorm_kernel<<<Mq, 256>>>(hidden, norm_w, p_h);

    // 2) projections
    launch_gemm(p_h, q_w, nullptr, p_qp, Dq,  Dq, 0);
    launch_gemm(p_h, k_w, nullptr, p_kp, Dq,  Dq, 0);
    launch_gemm(p_h, v_w, nullptr, p_vp, VDq, Dq, 0);
    launch_gemm(p_h, g_w, nullptr, p_gt, VDq, Dq, 0);
    ba_kernel<<<Mq / 4, 128>>>(p_h, b_w, a_w, A_log, dt_bias, p_bt, p_gd);

    // 3) causal conv + silu
    conv_silu_kernel<<<(Mq * Dq)  / 256, 256>>>(p_qp, conv_q_w, p_q, Dq);
    conv_silu_kernel<<<(Mq * Dq)  / 256, 256>>>(p_kp, conv_k_w, p_k, Dq);
    conv_silu_kernel<<<(Mq * VDq) / 256, 256>>>(p_vp, conv_v_w, p_v, VDq);

    // 4) l2 norm q, k (in place)
    l2norm_kernel<<<(Mq * Hq) / 8, 256>>>(p_q);
    l2norm_kernel<<<(Mq * Hq) / 8, 256>>>(p_k);

    // 5) gated delta rule scan
    scan_kernel<<<Bq * Hq * 2, 256>>>(p_q, p_k, p_v, p_gd, p_bt, p_o);

    // 6) gated per-head RMSNorm (in place on o)
    gated_rmsnorm_kernel<<<(Mq * Hq) / 8, 256>>>(p_o, o_norm_w, p_gt);

    // 7) output projection + residual -> x
    launch_gemm(p_o, o_w, hidden, p_x, Dq, VDq, 1);

    // 8) post norm
    rmsnorm_kernel<<<Mq, 256>>>(p_x, post_norm_w, p_h2);

    // 9) MLP
    launch_gemm(p_h2, gate_w, nullptr, p_gb, FFq, Dq, 0);
    launch_gemm(p_h2, up_w,   nullptr, p_ub, FFq, Dq, 0);
    act_kernel<<<(int)(((size_t)Mq * FFq / 4 + 255) / 256), 256>>>(p_gb, p_ub);
    launch_gemm(p_gb, down_w, p_x, out, Dq, FFq, 1);
}

// round 7
// speedup vs baseline: 2.2516x; 2.2516x over previous
#include <cuda_runtime.h>
#include <cuda_bf16.h>
#include <cstdint>

#define Bq 2
#define Tq 2048
#define Dq 1024
#define VDq 2048
#define FFq 2752
#define FFp 5632        // gate|up fused, padded
#define Hq 16
#define DKq 64
#define DVq 128
#define Mq (Bq*Tq)      // 4096

// ---------------- device scratch --------------------------------------------
__device__ float g_h   [Mq*(size_t)Dq];
__device__ float g_qkvg[Mq*(size_t)6144];
__device__ float g_q   [Mq*(size_t)Dq];
__device__ float g_k   [Mq*(size_t)Dq];
__device__ float g_v   [Mq*(size_t)VDq];
__device__ float g_bt  [Mq*(size_t)Hq];
__device__ float g_gd  [Mq*(size_t)Hq];     // exp(g) decay
__device__ float g_o   [Mq*(size_t)VDq];
__device__ float g_x   [Mq*(size_t)Dq];
__device__ float g_h2  [Mq*(size_t)Dq];
__device__ float g_gu  [Mq*(size_t)FFp];
__device__ __nv_bfloat16 g_Aexp [Mq*(size_t)8256];
__device__ __nv_bfloat16 g_Bqkvg[(size_t)6144*3072];
__device__ __nv_bfloat16 g_Bo   [(size_t)1024*6144];
__device__ __nv_bfloat16 g_Bmlp [(size_t)FFp*3072];
__device__ __nv_bfloat16 g_Bdwn [(size_t)1024*8256];

// ---------------- PTX helpers ------------------------------------------------
__device__ __forceinline__ uint32_t smem_u32(const void* p) {
    uint32_t a;
    asm("{ .reg .u64 t; cvta.to.shared.u64 t, %1; cvt.u32.u64 %0, t; }" : "=r"(a) : "l"(p));
    return a;
}
typedef unsigned long long ull;
__device__ __forceinline__ ull ffma2(ull a, ull b, ull c) {
    ull d; asm("fma.rn.f32x2 %0,%1,%2,%3;" : "=l"(d) : "l"(a), "l"(b), "l"(c)); return d;
}
__device__ __forceinline__ ull mul2(ull a, ull b) {
    ull d; asm("mul.rn.f32x2 %0,%1,%2;" : "=l"(d) : "l"(a), "l"(b)); return d;
}
__device__ __forceinline__ ull dup2(float x) {
    ull r; asm("mov.b64 %0, {%1,%1};" : "=l"(r) : "f"(x)); return r;
}
__device__ __forceinline__ float2 unpk(ull a) {
    float2 f; asm("mov.b64 {%0,%1}, %2;" : "=f"(f.x), "=f"(f.y) : "l"(a)); return f;
}
__device__ __forceinline__ float siluf(float x) { return x / (1.0f + __expf(-x)); }

#define SWZ(o) ((o) ^ (((o) >> 3) & 0x70))
#define CP16(d, s) asm volatile("cp.async.cg.shared.global [%0], [%1], 16;" :: "r"(d), "l"(s) : "memory")
#define CP4(d, s)  asm volatile("cp.async.ca.shared.global [%0], [%1], 4;"  :: "r"(d), "l"(s) : "memory")
#define CPCOMMIT() asm volatile("cp.async.commit_group;" ::: "memory")
#define CPWAIT1()  asm volatile("cp.async.wait_group 1;" ::: "memory")
#define CPWAIT2()  asm volatile("cp.async.wait_group 2;" ::: "memory")

#define LDMX4(r0,r1,r2,r3,addr) \
    asm volatile("ldmatrix.sync.aligned.m8n8.x4.shared.b16 {%0,%1,%2,%3}, [%4];" \
                 : "=r"(r0), "=r"(r1), "=r"(r2), "=r"(r3) : "r"(addr))

#define MMA16816(c, a, b) \
    asm volatile("mma.sync.aligned.m16n8k16.row.col.f32.bf16.bf16.f32 " \
                 "{%0,%1,%2,%3}, {%4,%5,%6,%7}, {%8,%9}, {%0,%1,%2,%3};" \
                 : "+f"((c)[0]), "+f"((c)[1]), "+f"((c)[2]), "+f"((c)[3]) \
                 : "r"((a)[0]), "r"((a)[1]), "r"((a)[2]), "r"((a)[3]), \
                   "r"((b)[0]), "r"((b)[1]))

// ---------------- split / transpose conversion kernels ----------------------
__global__ void split_rows(const float* __restrict__ in, __nv_bfloat16* __restrict__ out, int K) {
    size_t i = (size_t)blockIdx.x * 256 + threadIdx.x;
    if (i >= (size_t)Mq * K) return;
    size_t m = i / K; int kk = (int)(i % K);
    float x = in[i];
    __nv_bfloat16 hi = __float2bfloat16(x);
    __nv_bfloat16 lo = __float2bfloat16(x - __bfloat162float(hi));
    __nv_bfloat16* r = out + m * (size_t)(3 * K);
    r[kk] = hi; r[K + kk] = lo; r[2 * K + kk] = hi;   // A'' = [Ah|Al|Ah]
}

__global__ void splitT(const float* __restrict__ W, __nv_bfloat16* __restrict__ out, int K, int N) {
    // W[K][N] -> out[N][3K] = [Bh|Bh|Bl]
    __shared__ float tile[32][33];
    int n0 = blockIdx.x * 32, k0 = blockIdx.y * 32;
    for (int r = threadIdx.y; r < 32; r += 8)
        tile[r][threadIdx.x] = W[(size_t)(k0 + r) * N + n0 + threadIdx.x];
    __syncthreads();
    for (int r = threadIdx.y; r < 32; r += 8) {
        int n = n0 + r, kk = k0 + threadIdx.x;
        float x = tile[threadIdx.x][r];
        __nv_bfloat16 hi = __float2bfloat16(x);
        __nv_bfloat16 lo = __float2bfloat16(x - __bfloat162float(hi));
        __nv_bfloat16* orow = out + (size_t)n * (3 * K);
        orow[kk] = hi; orow[K + kk] = hi; orow[2 * K + kk] = lo;
    }
}

__global__ void act_split(const float* __restrict__ gu, __nv_bfloat16* __restrict__ out) {
    size_t i = (size_t)blockIdx.x * 256 + threadIdx.x;
    if (i >= (size_t)Mq * FFq) return;
    size_t m = i / FFq; int kk = (int)(i % FFq);
    float g = gu[m * FFp + kk], u = gu[m * FFp + FFq + kk];
    float a = siluf(g) * u;
    __nv_bfloat16 hi = __float2bfloat16(a);
    __nv_bfloat16 lo = __float2bfloat16(a - __bfloat162float(hi));
    __nv_bfloat16* r = out + m * (size_t)(3 * FFq);
    r[kk] = hi; r[FFq + kk] = lo; r[2 * FFq + kk] = hi;
}

// ---------------- bf16 mma.sync GEMM ------------------------------------------
// C[M][N] = A''[M][KK] @ B''[N][KK]^T (+R). 128x128 tile, BK=64, 4-stage cp.async.
#define STG_A 16384
#define STG_B 16384
#define NSTAGE 4
#define GSMEM (1024 + NSTAGE*(STG_A + STG_B))

__global__ void __launch_bounds__(256, 1)
gemm_tc(const __nv_bfloat16* __restrict__ A, const __nv_bfloat16* __restrict__ B,
        const float* __restrict__ R, float* __restrict__ C, int N, int KK, int addR) {
    extern __shared__ char dsm[];
    uint32_t base = smem_u32(dsm);
    uint32_t uA = (base + 1023) & ~1023u;
    uint32_t uB = uA + NSTAGE * STG_A;

    const int tid = threadIdx.x;
    const int wid = tid >> 5, lane = tid & 31;
    const int bm = blockIdx.y * 128;
    const int bn = blockIdx.x * 128;
    const int wm = (wid & 1) * 64;
    const int wn = (wid >> 1) * 32;
    const int nslab = KK >> 6;

    auto fill = [&](int stg, int slab) {
        int k0 = slab << 6;
        const __nv_bfloat16* Ab = A + (size_t)bm * KK + k0;
        const __nv_bfloat16* Bb = B + (size_t)bn * KK + k0;
        uint32_t sA = uA + stg * STG_A, sB = uB + stg * STG_B;
        #pragma unroll
        for (int i = 0; i < 8; i++) {
            int id = tid + (i << 8);
            int row = (id & 1023) >> 3, c = id & 7;
            if (id < 1024) CP16(sA + SWZ(row * 128 + c * 16), Ab + (size_t)row * KK + c * 8);
            else           CP16(sB + SWZ(row * 128 + c * 16), Bb + (size_t)row * KK + c * 8);
        }
        CPCOMMIT();
    };

    float acc[4][4][4];
    #pragma unroll
    for (int mt = 0; mt < 4; mt++)
        #pragma unroll
        for (int nt = 0; nt < 4; nt++)
            #pragma unroll
            for (int j = 0; j < 4; j++) acc[mt][nt][j] = 0.f;

    fill(0, 0);
    if (nslab > 1) fill(1, 1); else CPCOMMIT();
    if (nslab > 2) fill(2, 2); else CPCOMMIT();

    // ldmatrix lane addressing (constant per thread)
    const int a_row = (lane & 15);          // + wm + mt*16
    const int a_sel = (lane >> 4);          // 0/1 -> kchunk offset
    const int b_row = (lane & 7) + ((lane >> 4) << 3);  // + wn + bt*16
    const int b_sel = (lane >> 3) & 1;

    for (int s = 0; s < nslab; s++) {
        CPWAIT2();
        __syncthreads();
        uint32_t sA = uA + (s % NSTAGE) * STG_A;
        uint32_t sB = uB + (s % NSTAGE) * STG_B;
        #pragma unroll
        for (int ks = 0; ks < 4; ks++) {
            uint32_t a[4][4], b[4][2];
            #pragma unroll
            for (int mt = 0; mt < 4; mt++) {
                uint32_t addr = sA + SWZ((wm + mt * 16 + a_row) * 128 + (ks * 2 + a_sel) * 16);
                LDMX4(a[mt][0], a[mt][1], a[mt][2], a[mt][3], addr);
            }
            #pragma unroll
            for (int bt = 0; bt < 2; bt++) {
                uint32_t addr = sB + SWZ((wn + bt * 16 + b_row) * 128 + (ks * 2 + b_sel) * 16);
                LDMX4(b[bt*2][0], b[bt*2][1], b[bt*2+1][0], b[bt*2+1][1], addr);
            }
            #pragma unroll
            for (int mt = 0; mt < 4; mt++)
                #pragma unroll
                for (int nt = 0; nt < 4; nt++)
                    MMA16816(acc[mt][nt], a[mt], b[nt]);
        }
        __syncthreads();
        if (s + 3 < nslab) fill((s + 3) % NSTAGE, s + 3);
        else CPCOMMIT();
    }

    // epilogue: write fragments
    #pragma unroll
    for (int mt = 0; mt < 4; mt++) {
        #pragma unroll
        for (int h = 0; h < 2; h++) {
            int row = bm + wm + mt * 16 + (lane >> 2) + h * 8;
            float* crow = C + (size_t)row * N + bn + wn + 2 * (lane & 3);
            const float* rrow = addR ? (R + (size_t)row * N + bn + wn + 2 * (lane & 3)) : nullptr;
            #pragma unroll
            for (int nt = 0; nt < 4; nt++) {
                float2 ov = make_float2(acc[mt][nt][h*2], acc[mt][nt][h*2+1]);
                if (addR) {
                    float2 rv = *(const float2*)(rrow + nt * 8);
                    ov.x += rv.x; ov.y += rv.y;
                }
                *(float2*)(crow + nt * 8) = ov;
            }
        }
    }
}

// ---------------- small elementwise kernels ----------------------------------
__global__ void rmsnorm_kernel(const float* __restrict__ x, const float* __restrict__ w,
                               float* __restrict__ out) {
    int row = blockIdx.x;
    float4 v = ((const float4*)(x + (size_t)row * Dq))[threadIdx.x];
    float ss = v.x*v.x + v.y*v.y + v.z*v.z + v.w*v.w;
    #pragma unroll
    for (int o = 16; o; o >>= 1) ss += __shfl_xor_sync(0xffffffffu, ss, o);
    __shared__ float red[8];
    int wd = threadIdx.x >> 5, ln = threadIdx.x & 31;
    if (ln == 0) red[wd] = ss;
    __syncthreads();
    float tot = red[0]+red[1]+red[2]+red[3]+red[4]+red[5]+red[6]+red[7];
    float r = rsqrtf(tot * (1.0f / Dq) + 1e-6f);
    float4 wv = ((const float4*)w)[threadIdx.x];
    ((float4*)(out + (size_t)row * Dq))[threadIdx.x] =
        make_float4(v.x*r*wv.x, v.y*r*wv.y, v.z*r*wv.z, v.w*r*wv.w);
}

__global__ void conv_silu_kernel(const float* __restrict__ in, int stride,
                                 const float* __restrict__ w,
                                 float* __restrict__ out, int C) {
    size_t idx = (size_t)blockIdx.x * 256 + threadIdx.x;
    if (idx >= (size_t)Mq * C) return;
    int c = (int)(idx % C);
    size_t bt = idx / C;
    int t = (int)(bt % Tq);
    const float* p = in + bt * (size_t)stride + c;
    float4 wv = ((const float4*)w)[c];
    float acc = wv.w * p[0];
    if (t >= 1) acc += wv.z * p[-(ptrdiff_t)stride];
    if (t >= 2) acc += wv.y * p[-2 * (ptrdiff_t)stride];
    if (t >= 3) acc += wv.x * p[-3 * (ptrdiff_t)stride];
    out[idx] = siluf(acc);
}

__global__ void l2norm_kernel(float* __restrict__ p, float scale) {
    int vec = blockIdx.x * 8 + (threadIdx.x >> 5);
    int lane = threadIdx.x & 31;
    float2* vp = (float2*)(p + (size_t)vec * DKq);
    float2 v = vp[lane];
    float ss = v.x*v.x + v.y*v.y;
    #pragma unroll
    for (int o = 16; o; o >>= 1) ss += __shfl_xor_sync(0xffffffffu, ss, o);
    float r = rsqrtf(ss + 1e-6f) * scale;
    vp[lane] = make_float2(v.x * r, v.y * r);
}

__global__ void ba_kernel(const float* __restrict__ h, const float* __restrict__ b_w,
                          const float* __restrict__ a_w, const float* __restrict__ A_log,
                          const float* __restrict__ dt_bias,
                          float* __restrict__ beta, float* __restrict__ dec) {
    int row = blockIdx.x * 4 + (threadIdx.x >> 5);
    int lane = threadIdx.x & 31;
    int c = lane & 15;
    const float* W = (lane < 16) ? b_w : a_w;
    const float* hr = h + (size_t)row * Dq;
    float a0 = 0.f, a1 = 0.f, a2 = 0.f, a3 = 0.f;
    for (int kk = 0; kk < Dq; kk += 4) {
        a0 += hr[kk+0] * W[(kk+0)*Hq + c];
        a1 += hr[kk+1] * W[(kk+1)*Hq + c];
        a2 += hr[kk+2] * W[(kk+2)*Hq + c];
        a3 += hr[kk+3] * W[(kk+3)*Hq + c];
    }
    float acc = (a0 + a1) + (a2 + a3);
    if (lane < 16) {
        beta[(size_t)row * Hq + c] = 1.0f / (1.0f + __expf(-acc));
    } else {
        float xv = acc + dt_bias[c];
        float sp = fmaxf(xv, 0.f) + log1pf(__expf(-fabsf(xv)));
        dec[(size_t)row * Hq + c] = __expf(-__expf(A_log[c]) * sp);
    }
}

__global__ void gated_rmsnorm_kernel(float* __restrict__ o, const float* __restrict__ w,
                                     const float* __restrict__ gate, int gstride) {
    int vec = blockIdx.x * 8 + (threadIdx.x >> 5);
    int lane = threadIdx.x & 31;
    int m = vec >> 4, hh = vec & 15;
    float4* op = (float4*)(o + (size_t)vec * DVq);
    const float4* gp = (const float4*)(gate + (size_t)m * gstride + hh * DVq);
    float4 v = op[lane];
    float ss = v.x*v.x + v.y*v.y + v.z*v.z + v.w*v.w;
    #pragma unroll
    for (int off = 16; off; off >>= 1) ss += __shfl_xor_sync(0xffffffffu, ss, off);
    float r = rsqrtf(ss * (1.0f / DVq) + 1e-6f);
    float4 wv = ((const float4*)w)[lane];
    float4 g = gp[lane];
    op[lane] = make_float4(v.x*r*wv.x*siluf(g.x), v.y*r*wv.y*siluf(g.y),
                           v.z*r*wv.z*siluf(g.z), v.w*r*wv.w*siluf(g.w));
}

// ---------------- gated delta-rule scan (cp.async ring + f32x2) --------------
#define RSTRIDE 196
__global__ void __launch_bounds__(256)
scan_kernel(const float* __restrict__ q, const float* __restrict__ k,
            const float* __restrict__ v, const float* __restrict__ dec,
            const float* __restrict__ bt, float* __restrict__ o) {
    __shared__ float ring[16 * RSTRIDE];
    int half = blockIdx.x & 1;
    int bh = blockIdx.x >> 1;
    int b = bh >> 4, h = bh & 15;
    int tid = threadIdx.x;
    int colL = tid >> 2, sub = tid & 3;
    int col = half * 64 + colL;

    size_t rowBase = (size_t)b * Tq;
    const float* kb = k + rowBase * Dq + h * DKq;
    const float* qb = q + rowBase * Dq + h * DKq;
    const float* vb = v + rowBase * VDq + h * DVq + half * 64;
    const float* db = dec + rowBase * Hq + h;
    const float* bb = bt + rowBase * Hq + h;
    float* ob = o + rowBase * VDq + h * DVq + col;

    uint32_t ringU = smem_u32(ring);

    auto fill = [&](int hf, int blk) {
        #pragma unroll
        for (int rep = 0; rep < 2; rep++) {
            int idx = tid + rep * 256;
            if (idx < 400) {
                int sid = idx / 50, slot = idx % 50;
                int t = blk * 8 + sid;
                uint32_t sb = ringU + ((hf * 8 + sid) * RSTRIDE) * 4;
                if (slot < 16)       CP16(sb + slot * 16,          kb + (size_t)t * Dq  + slot * 4);
                else if (slot < 32)  CP16(sb + 256 + (slot-16)*16, qb + (size_t)t * Dq  + (slot-16) * 4);
                else if (slot < 48)  CP16(sb + 512 + (slot-32)*16, vb + (size_t)t * VDq + (slot-32) * 4);
                else if (slot == 48) CP4 (sb + 768,                db + (size_t)t * Hq);
                else                 CP4 (sb + 772,                bb + (size_t)t * Hq);
            }
        }
        CPCOMMIT();
    };

    ull S[8];
    #pragma unroll
    for (int p = 0; p < 8; p++) S[p] = 0ull;

    fill(0, 0);
    fill(1, 1);

    for (int blk = 0; blk < 256; blk++) {
        CPWAIT1();
        __syncthreads();
        int hf = blk & 1;
        #pragma unroll 1
        for (int j = 0; j < 8; j++) {
            const float* st = &ring[(hf * 8 + j) * RSTRIDE];
            const ull* kp = (const ull*)(st + sub * 16);
            const ull* qp = (const ull*)(st + 64 + sub * 16);
            float vt = st[128 + colL];
            float decay = st[192], bet = st[193];
            ull dpk = dup2(decay);
            ull kr[8], qr[8];
            #pragma unroll
            for (int p = 0; p < 8; p++) { kr[p] = kp[p]; qr[p] = qp[p]; }
            ull vpp = 0ull;
            #pragma unroll
            for (int p = 0; p < 8; p++) {
                S[p] = mul2(S[p], dpk);
                vpp = ffma2(kr[p], S[p], vpp);
            }
            float2 vpf = unpk(vpp);
            float vp = vpf.x + vpf.y;
            vp += __shfl_xor_sync(0xffffffffu, vp, 1);
            vp += __shfl_xor_sync(0xffffffffu, vp, 2);
            float u = bet * (vt - vp);
            ull up = dup2(u);
            ull opp = 0ull;
            #pragma unroll
            for (int p = 0; p < 8; p++) {
                S[p] = ffma2(kr[p], up, S[p]);
                opp = ffma2(qr[p], S[p], opp);
            }
            float2 otf = unpk(opp);
            float ot = otf.x + otf.y;
            ot += __shfl_xor_sync(0xffffffffu, ot, 1);
            ot += __shfl_xor_sync(0xffffffffu, ot, 2);
            if (sub == 0) ob[(size_t)(blk * 8 + j) * VDq] = ot;
        }
        __syncthreads();
        if (blk + 2 < 256) fill(hf, blk + 2);
        else CPCOMMIT();
    }
}

// ---------------- host orchestration -----------------------------------------
static inline void launch_gemm(const __nv_bfloat16* A, const __nv_bfloat16* B,
                               const float* R, float* C, int N, int KK, int addR) {
    dim3 grid(N / 128, Mq / 128);
    gemm_tc<<<grid, 256, GSMEM>>>(A, B, R, C, N, KK, addR);
}

extern "C" void kernel_launch(void* const* d_in, const int* in_sizes, int n_in,
                              void* d_out, int out_size) {
    const float* hidden   = (const float*)d_in[0];
    const float* norm_w   = (const float*)d_in[1];
    const float* q_w      = (const float*)d_in[2];
    const float* k_w      = (const float*)d_in[3];
    const float* v_w      = (const float*)d_in[4];
    const float* b_w      = (const float*)d_in[5];
    const float* a_w      = (const float*)d_in[6];
    const float* A_log    = (const float*)d_in[7];
    const float* dt_bias  = (const float*)d_in[8];
    const float* conv_q_w = (const float*)d_in[9];
    const float* conv_k_w = (const float*)d_in[10];
    const float* conv_v_w = (const float*)d_in[11];
    const float* g_wm     = (const float*)d_in[12];
    const float* o_norm_w = (const float*)d_in[13];
    const float* o_w      = (const float*)d_in[14];
    const float* post_w   = (const float*)d_in[15];
    const float* gate_w   = (const float*)d_in[16];
    const float* up_w     = (const float*)d_in[17];
    const float* down_w   = (const float*)d_in[18];
    float* out = (float*)d_out;

    float *p_h, *p_qkvg, *p_q, *p_k, *p_v, *p_bt, *p_gd, *p_o, *p_x, *p_h2, *p_gu;
    __nv_bfloat16 *p_A, *p_Bqkvg, *p_Bo, *p_Bmlp, *p_Bdwn;
    cudaGetSymbolAddress((void**)&p_h, g_h);
    cudaGetSymbolAddress((void**)&p_qkvg, g_qkvg);
    cudaGetSymbolAddress((void**)&p_q, g_q);
    cudaGetSymbolAddress((void**)&p_k, g_k);
    cudaGetSymbolAddress((void**)&p_v, g_v);
    cudaGetSymbolAddress((void**)&p_bt, g_bt);
    cudaGetSymbolAddress((void**)&p_gd, g_gd);
    cudaGetSymbolAddress((void**)&p_o, g_o);
    cudaGetSymbolAddress((void**)&p_x, g_x);
    cudaGetSymbolAddress((void**)&p_h2, g_h2);
    cudaGetSymbolAddress((void**)&p_gu, g_gu);
    cudaGetSymbolAddress((void**)&p_A, g_Aexp);
    cudaGetSymbolAddress((void**)&p_Bqkvg, g_Bqkvg);
    cudaGetSymbolAddress((void**)&p_Bo, g_Bo);
    cudaGetSymbolAddress((void**)&p_Bmlp, g_Bmlp);
    cudaGetSymbolAddress((void**)&p_Bdwn, g_Bdwn);

    cudaFuncSetAttribute(gemm_tc, cudaFuncAttributeMaxDynamicSharedMemorySize, GSMEM);

    // weight conversion (B'' = [Bh|Bh|Bl], transposed to [N][3K])
    splitT<<<dim3(32, 32), dim3(32, 8)>>>(q_w,    p_Bqkvg,                        1024, 1024);
    splitT<<<dim3(32, 32), dim3(32, 8)>>>(k_w,    p_Bqkvg + (size_t)1024 * 3072,  1024, 1024);
    splitT<<<dim3(64, 32), dim3(32, 8)>>>(v_w,    p_Bqkvg + (size_t)2048 * 3072,  1024, 2048);
    splitT<<<dim3(64, 32), dim3(32, 8)>>>(g_wm,   p_Bqkvg + (size_t)4096 * 3072,  1024, 2048);
    splitT<<<dim3(32, 64), dim3(32, 8)>>>(o_w,    p_Bo,                           2048, 1024);
    splitT<<<dim3(86, 32), dim3(32, 8)>>>(gate_w, p_Bmlp,                         1024, 2752);
    splitT<<<dim3(86, 32), dim3(32, 8)>>>(up_w,   p_Bmlp + (size_t)2752 * 3072,   1024, 2752);
    cudaMemsetAsync(p_Bmlp + (size_t)5504 * 3072, 0, (size_t)128 * 3072 * sizeof(__nv_bfloat16));
    splitT<<<dim3(32, 86), dim3(32, 8)>>>(down_w, p_Bdwn,                         2752, 1024);

    // 1) pre-norm + split
    rmsnorm_kernel<<<Mq, 256>>>(hidden, norm_w, p_h);
    split_rows<<<(int)(((size_t)Mq * 1024 + 255) / 256), 256>>>(p_h, p_A, 1024);

    // 2) fused q|k|v|gate projection (N=6144, KK=3072)
    launch_gemm(p_A, p_Bqkvg, nullptr, p_qkvg, 6144, 3072, 0);
    ba_kernel<<<Mq / 4, 128>>>(p_h, b_w, a_w, A_log, dt_bias, p_bt, p_gd);

    // 3) conv + silu from qkvg slices
    conv_silu_kernel<<<(int)(((size_t)Mq * 1024 + 255) / 256), 256>>>(p_qkvg,        6144, conv_q_w, p_q, 1024);
    conv_silu_kernel<<<(int)(((size_t)Mq * 1024 + 255) / 256), 256>>>(p_qkvg + 1024, 6144, conv_k_w, p_k, 1024);
    conv_silu_kernel<<<(int)(((size_t)Mq * 2048 + 255) / 256), 256>>>(p_qkvg + 2048, 6144, conv_v_w, p_v, 2048);

    // 4) l2norm (q pre-scaled by dk^-0.5)
    l2norm_kernel<<<(Mq * Hq) / 8, 256>>>(p_q, 0.125f);
    l2norm_kernel<<<(Mq * Hq) / 8, 256>>>(p_k, 1.0f);

    // 5) scan
    scan_kernel<<<Bq * Hq * 2, 256>>>(p_q, p_k, p_v, p_gd, p_bt, p_o);

    // 6) gated per-head RMSNorm (gate slice from qkvg)
    gated_rmsnorm_kernel<<<(Mq * Hq) / 8, 256>>>(p_o, o_norm_w, p_qkvg + 4096, 6144);

    // 7) output projection + residual
    split_rows<<<(int)(((size_t)Mq * 2048 + 255) / 256), 256>>>(p_o, p_A, 2048);
    launch_gemm(p_A, p_Bo, hidden, p_x, 1024, 6144, 1);

    // 8) post norm + MLP
    rmsnorm_kernel<<<Mq, 256>>>(p_x, post_w, p_h2);
    split_rows<<<(int)(((size_t)Mq * 1024 + 255) / 256), 256>>>(p_h2, p_A, 1024);
    launch_gemm(p_A, p_Bmlp, nullptr, p_gu, FFp, 3072, 0);
    act_split<<<(int)(((size_t)Mq * FFq + 255) / 256), 256>>>(p_gu, p_A);
    launch_gemm(p_A, p_Bdwn, p_x, out, 1024, 8256, 1);
}

// round 8
// speedup vs baseline: 2.5976x; 1.1536x over previous
#include <cuda_runtime.h>
#include <cuda_bf16.h>
#include <cstdint>

#define Bq 2
#define Tq 2048
#define Dq 1024
#define VDq 2048
#define FFq 2752
#define FFp 5632        // gate|up fused, padded
#define Hq 16
#define DKq 64
#define DVq 128
#define Mq (Bq*Tq)      // 4096

// ---------------- device scratch --------------------------------------------
__device__ float g_h   [Mq*(size_t)Dq];
__device__ float g_qkvg[Mq*(size_t)6144];
__device__ float g_q   [Mq*(size_t)Dq];
__device__ float g_k   [Mq*(size_t)Dq];
__device__ float g_v   [Mq*(size_t)VDq];
__device__ float g_bt  [Mq*(size_t)Hq];
__device__ float g_gd  [Mq*(size_t)Hq];     // exp(g) decay
__device__ float g_o   [Mq*(size_t)VDq];
__device__ float g_x   [Mq*(size_t)Dq];
__device__ float g_gu  [Mq*(size_t)FFp];
__device__ __nv_bfloat16 g_Aexp [Mq*(size_t)8256];
__device__ __nv_bfloat16 g_Bqkvg[(size_t)6144*3072];
__device__ __nv_bfloat16 g_Bo   [(size_t)1024*6144];
__device__ __nv_bfloat16 g_Bmlp [(size_t)FFp*3072];
__device__ __nv_bfloat16 g_Bdwn [(size_t)1024*8256];

// ---------------- PTX helpers ------------------------------------------------
__device__ __forceinline__ uint32_t smem_u32(const void* p) {
    uint32_t a;
    asm("{ .reg .u64 t; cvta.to.shared.u64 t, %1; cvt.u32.u64 %0, t; }" : "=r"(a) : "l"(p));
    return a;
}
typedef unsigned long long ull;
__device__ __forceinline__ ull ffma2(ull a, ull b, ull c) {
    ull d; asm("fma.rn.f32x2 %0,%1,%2,%3;" : "=l"(d) : "l"(a), "l"(b), "l"(c)); return d;
}
__device__ __forceinline__ ull mul2(ull a, ull b) {
    ull d; asm("mul.rn.f32x2 %0,%1,%2;" : "=l"(d) : "l"(a), "l"(b)); return d;
}
__device__ __forceinline__ ull dup2(float x) {
    ull r; asm("mov.b64 %0, {%1,%1};" : "=l"(r) : "f"(x)); return r;
}
__device__ __forceinline__ float2 unpk(ull a) {
    float2 f; asm("mov.b64 {%0,%1}, %2;" : "=f"(f.x), "=f"(f.y) : "l"(a)); return f;
}
__device__ __forceinline__ float siluf(float x) { return x / (1.0f + __expf(-x)); }

// pack 4 floats -> 4 bf16 (8 bytes): hi parts
__device__ __forceinline__ void split4(float4 v, ull& hi, ull& lo) {
    __nv_bfloat16 h0 = __float2bfloat16(v.x), h1 = __float2bfloat16(v.y),
                  h2 = __float2bfloat16(v.z), h3 = __float2bfloat16(v.w);
    __nv_bfloat16 l0 = __float2bfloat16(v.x - __bfloat162float(h0));
    __nv_bfloat16 l1 = __float2bfloat16(v.y - __bfloat162float(h1));
    __nv_bfloat16 l2 = __float2bfloat16(v.z - __bfloat162float(h2));
    __nv_bfloat16 l3 = __float2bfloat16(v.w - __bfloat162float(h3));
    ushort4 hu = make_ushort4(__bfloat16_as_ushort(h0), __bfloat16_as_ushort(h1),
                              __bfloat16_as_ushort(h2), __bfloat16_as_ushort(h3));
    ushort4 lu = make_ushort4(__bfloat16_as_ushort(l0), __bfloat16_as_ushort(l1),
                              __bfloat16_as_ushort(l2), __bfloat16_as_ushort(l3));
    hi = *(ull*)&hu; lo = *(ull*)&lu;
}

#define SWZ(o) ((o) ^ (((o) >> 3) & 0x70))
#define CP16(d, s) asm volatile("cp.async.cg.shared.global [%0], [%1], 16;" :: "r"(d), "l"(s) : "memory")
#define CP4(d, s)  asm volatile("cp.async.ca.shared.global [%0], [%1], 4;"  :: "r"(d), "l"(s) : "memory")
#define CPCOMMIT() asm volatile("cp.async.commit_group;" ::: "memory")
#define CPWAIT1()  asm volatile("cp.async.wait_group 1;" ::: "memory")
#define CPWAIT2()  asm volatile("cp.async.wait_group 2;" ::: "memory")

#define LDMX4(r0,r1,r2,r3,addr) \
    asm volatile("ldmatrix.sync.aligned.m8n8.x4.shared.b16 {%0,%1,%2,%3}, [%4];" \
                 : "=r"(r0), "=r"(r1), "=r"(r2), "=r"(r3) : "r"(addr))

#define MMA16816(c, a, b) \
    asm volatile("mma.sync.aligned.m16n8k16.row.col.f32.bf16.bf16.f32 " \
                 "{%0,%1,%2,%3}, {%4,%5,%6,%7}, {%8,%9}, {%0,%1,%2,%3};" \
                 : "+f"((c)[0]), "+f"((c)[1]), "+f"((c)[2]), "+f"((c)[3]) \
                 : "r"((a)[0]), "r"((a)[1]), "r"((a)[2]), "r"((a)[3]), \
                   "r"((b)[0]), "r"((b)[1]))

// ---------------- weight split/transpose -------------------------------------
__global__ void splitT(const float* __restrict__ W, __nv_bfloat16* __restrict__ out, int K, int N) {
    // W[K][N] -> out[N][3K] = [Bh|Bh|Bl]
    __shared__ float tile[32][33];
    int n0 = blockIdx.x * 32, k0 = blockIdx.y * 32;
    for (int r = threadIdx.y; r < 32; r += 8)
        tile[r][threadIdx.x] = W[(size_t)(k0 + r) * N + n0 + threadIdx.x];
    __syncthreads();
    for (int r = threadIdx.y; r < 32; r += 8) {
        int n = n0 + r, kk = k0 + threadIdx.x;
        float x = tile[threadIdx.x][r];
        __nv_bfloat16 hi = __float2bfloat16(x);
        __nv_bfloat16 lo = __float2bfloat16(x - __bfloat162float(hi));
        __nv_bfloat16* orow = out + (size_t)n * (3 * K);
        orow[kk] = hi; orow[K + kk] = hi; orow[2 * K + kk] = lo;
    }
}

__global__ void act_split(const float* __restrict__ gu, __nv_bfloat16* __restrict__ out) {
    size_t i = (size_t)blockIdx.x * 256 + threadIdx.x;
    if (i >= (size_t)Mq * FFq) return;
    size_t m = i / FFq; int kk = (int)(i % FFq);
    float g = gu[m * FFp + kk], u = gu[m * FFp + FFq + kk];
    float a = siluf(g) * u;
    __nv_bfloat16 hi = __float2bfloat16(a);
    __nv_bfloat16 lo = __float2bfloat16(a - __bfloat162float(hi));
    __nv_bfloat16* r = out + m * (size_t)(3 * FFq);
    r[kk] = hi; r[FFq + kk] = lo; r[2 * FFq + kk] = hi;
}

// ---------------- bf16 mma.sync GEMM (unchanged from R7) ----------------------
#define STG_A 16384
#define STG_B 16384
#define NSTAGE 4
#define GSMEM (1024 + NSTAGE*(STG_A + STG_B))

__global__ void __launch_bounds__(256, 1)
gemm_tc(const __nv_bfloat16* __restrict__ A, const __nv_bfloat16* __restrict__ B,
        const float* __restrict__ R, float* __restrict__ C, int N, int KK, int addR) {
    extern __shared__ char dsm[];
    uint32_t base = smem_u32(dsm);
    uint32_t uA = (base + 1023) & ~1023u;
    uint32_t uB = uA + NSTAGE * STG_A;

    const int tid = threadIdx.x;
    const int wid = tid >> 5, lane = tid & 31;
    const int bm = blockIdx.y * 128;
    const int bn = blockIdx.x * 128;
    const int wm = (wid & 1) * 64;
    const int wn = (wid >> 1) * 32;
    const int nslab = KK >> 6;

    auto fill = [&](int stg, int slab) {
        int k0 = slab << 6;
        const __nv_bfloat16* Ab = A + (size_t)bm * KK + k0;
        const __nv_bfloat16* Bb = B + (size_t)bn * KK + k0;
        uint32_t sA = uA + stg * STG_A, sB = uB + stg * STG_B;
        #pragma unroll
        for (int i = 0; i < 8; i++) {
            int id = tid + (i << 8);
            int row = (id & 1023) >> 3, c = id & 7;
            if (id < 1024) CP16(sA + SWZ(row * 128 + c * 16), Ab + (size_t)row * KK + c * 8);
            else           CP16(sB + SWZ(row * 128 + c * 16), Bb + (size_t)row * KK + c * 8);
        }
        CPCOMMIT();
    };

    float acc[4][4][4];
    #pragma unroll
    for (int mt = 0; mt < 4; mt++)
        #pragma unroll
        for (int nt = 0; nt < 4; nt++)
            #pragma unroll
            for (int j = 0; j < 4; j++) acc[mt][nt][j] = 0.f;

    fill(0, 0);
    if (nslab > 1) fill(1, 1); else CPCOMMIT();
    if (nslab > 2) fill(2, 2); else CPCOMMIT();

    const int a_row = (lane & 15);
    const int a_sel = (lane >> 4);
    const int b_row = (lane & 7) + ((lane >> 4) << 3);
    const int b_sel = (lane >> 3) & 1;

    for (int s = 0; s < nslab; s++) {
        CPWAIT2();
        __syncthreads();
        uint32_t sA = uA + (s % NSTAGE) * STG_A;
        uint32_t sB = uB + (s % NSTAGE) * STG_B;
        #pragma unroll
        for (int ks = 0; ks < 4; ks++) {
            uint32_t a[4][4], b[4][2];
            #pragma unroll
            for (int mt = 0; mt < 4; mt++) {
                uint32_t addr = sA + SWZ((wm + mt * 16 + a_row) * 128 + (ks * 2 + a_sel) * 16);
                LDMX4(a[mt][0], a[mt][1], a[mt][2], a[mt][3], addr);
            }
            #pragma unroll
            for (int bt = 0; bt < 2; bt++) {
                uint32_t addr = sB + SWZ((wn + bt * 16 + b_row) * 128 + (ks * 2 + b_sel) * 16);
                LDMX4(b[bt*2][0], b[bt*2][1], b[bt*2+1][0], b[bt*2+1][1], addr);
            }
            #pragma unroll
            for (int mt = 0; mt < 4; mt++)
                #pragma unroll
                for (int nt = 0; nt < 4; nt++)
                    MMA16816(acc[mt][nt], a[mt], b[nt]);
        }
        __syncthreads();
        if (s + 3 < nslab) fill((s + 3) % NSTAGE, s + 3);
        else CPCOMMIT();
    }

    #pragma unroll
    for (int mt = 0; mt < 4; mt++) {
        #pragma unroll
        for (int h = 0; h < 2; h++) {
            int row = bm + wm + mt * 16 + (lane >> 2) + h * 8;
            float* crow = C + (size_t)row * N + bn + wn + 2 * (lane & 3);
            const float* rrow = addR ? (R + (size_t)row * N + bn + wn + 2 * (lane & 3)) : nullptr;
            #pragma unroll
            for (int nt = 0; nt < 4; nt++) {
                float2 ov = make_float2(acc[mt][nt][h*2], acc[mt][nt][h*2+1]);
                if (addR) {
                    float2 rv = *(const float2*)(rrow + nt * 8);
                    ov.x += rv.x; ov.y += rv.y;
                }
                *(float2*)(crow + nt * 8) = ov;
            }
        }
    }
}

// ---------------- fused RMSNorm -> (optional f32) + bf16 split ---------------
__global__ void rmsnorm_split_kernel(const float* __restrict__ x, const float* __restrict__ w,
                                     float* __restrict__ outf,
                                     __nv_bfloat16* __restrict__ outb) {
    int row = blockIdx.x;
    float4 v = ((const float4*)(x + (size_t)row * Dq))[threadIdx.x];
    float ss = v.x*v.x + v.y*v.y + v.z*v.z + v.w*v.w;
    #pragma unroll
    for (int o = 16; o; o >>= 1) ss += __shfl_xor_sync(0xffffffffu, ss, o);
    __shared__ float red[8];
    int wd = threadIdx.x >> 5, ln = threadIdx.x & 31;
    if (ln == 0) red[wd] = ss;
    __syncthreads();
    float tot = red[0]+red[1]+red[2]+red[3]+red[4]+red[5]+red[6]+red[7];
    float r = rsqrtf(tot * (1.0f / Dq) + 1e-6f);
    float4 wv = ((const float4*)w)[threadIdx.x];
    float4 ov = make_float4(v.x*r*wv.x, v.y*r*wv.y, v.z*r*wv.z, v.w*r*wv.w);
    if (outf) ((float4*)(outf + (size_t)row * Dq))[threadIdx.x] = ov;
    ull hi, lo; split4(ov, hi, lo);
    ull* rb = (ull*)(outb + (size_t)row * 3072 + threadIdx.x * 4);
    rb[0] = hi;                  // Ah
    *(ull*)((__nv_bfloat16*)rb + 1024) = lo;   // Al
    *(ull*)((__nv_bfloat16*)rb + 2048) = hi;   // Ah
}

// ---------------- fused conv+silu+l2norm for q/k ------------------------------
__global__ void conv_l2_kernel(const float* __restrict__ in, int stride,
                               const float* __restrict__ w,
                               float* __restrict__ out, float scale) {
    int vec = blockIdx.x * 8 + (threadIdx.x >> 5);   // bt*16 + h
    int lane = threadIdx.x & 31;
    int bt = vec >> 4, h = vec & 15;
    int t = bt & (Tq - 1);
    int c = h * 64 + lane * 2;
    const float* p = in + (size_t)bt * stride + c;
    float2 x0 = *(const float2*)p;
    float2 x1 = (t >= 1) ? *(const float2*)(p - stride)     : make_float2(0.f, 0.f);
    float2 x2 = (t >= 2) ? *(const float2*)(p - 2 * stride) : make_float2(0.f, 0.f);
    float2 x3 = (t >= 3) ? *(const float2*)(p - 3 * stride) : make_float2(0.f, 0.f);
    float4 w0 = ((const float4*)w)[c];
    float4 w1 = ((const float4*)w)[c + 1];
    float a0 = w0.w*x0.x + w0.z*x1.x + w0.y*x2.x + w0.x*x3.x;
    float a1 = w1.w*x0.y + w1.z*x1.y + w1.y*x2.y + w1.x*x3.y;
    a0 = siluf(a0); a1 = siluf(a1);
    float ss = a0*a0 + a1*a1;
    #pragma unroll
    for (int o = 16; o; o >>= 1) ss += __shfl_xor_sync(0xffffffffu, ss, o);
    float r = rsqrtf(ss + 1e-6f) * scale;
    *(float2*)(out + (size_t)bt * Dq + c) = make_float2(a0 * r, a1 * r);
}

// ---------------- conv+silu for v (elementwise) -------------------------------
__global__ void conv_silu_kernel(const float* __restrict__ in, int stride,
                                 const float* __restrict__ w,
                                 float* __restrict__ out, int C) {
    size_t idx = (size_t)blockIdx.x * 256 + threadIdx.x;
    if (idx >= (size_t)Mq * C) return;
    int c = (int)(idx % C);
    size_t bt = idx / C;
    int t = (int)(bt % Tq);
    const float* p = in + bt * (size_t)stride + c;
    float4 wv = ((const float4*)w)[c];
    float acc = wv.w * p[0];
    if (t >= 1) acc += wv.z * p[-(ptrdiff_t)stride];
    if (t >= 2) acc += wv.y * p[-2 * (ptrdiff_t)stride];
    if (t >= 3) acc += wv.x * p[-3 * (ptrdiff_t)stride];
    out[idx] = siluf(acc);
}

__global__ void ba_kernel(const float* __restrict__ h, const float* __restrict__ b_w,
                          const float* __restrict__ a_w, const float* __restrict__ A_log,
                          const float* __restrict__ dt_bias,
                          float* __restrict__ beta, float* __restrict__ dec) {
    int row = blockIdx.x * 4 + (threadIdx.x >> 5);
    int lane = threadIdx.x & 31;
    int c = lane & 15;
    const float* W = (lane < 16) ? b_w : a_w;
    const float* hr = h + (size_t)row * Dq;
    float a0 = 0.f, a1 = 0.f, a2 = 0.f, a3 = 0.f;
    for (int kk = 0; kk < Dq; kk += 4) {
        a0 += hr[kk+0] * W[(kk+0)*Hq + c];
        a1 += hr[kk+1] * W[(kk+1)*Hq + c];
        a2 += hr[kk+2] * W[(kk+2)*Hq + c];
        a3 += hr[kk+3] * W[(kk+3)*Hq + c];
    }
    float acc = (a0 + a1) + (a2 + a3);
    if (lane < 16) {
        beta[(size_t)row * Hq + c] = 1.0f / (1.0f + __expf(-acc));
    } else {
        float xv = acc + dt_bias[c];
        float sp = fmaxf(xv, 0.f) + log1pf(__expf(-fabsf(xv)));
        dec[(size_t)row * Hq + c] = __expf(-__expf(A_log[c]) * sp);
    }
}

// ---------------- fused gated RMSNorm -> bf16 split ---------------------------
__global__ void gated_split_kernel(const float* __restrict__ o, const float* __restrict__ w,
                                   const float* __restrict__ gate, int gstride,
                                   __nv_bfloat16* __restrict__ outb) {
    int vec = blockIdx.x * 8 + (threadIdx.x >> 5);
    int lane = threadIdx.x & 31;
    int m = vec >> 4, hh = vec & 15;
    const float4* op = (const float4*)(o + (size_t)vec * DVq);
    const float4* gp = (const float4*)(gate + (size_t)m * gstride + hh * DVq);
    float4 v = op[lane];
    float ss = v.x*v.x + v.y*v.y + v.z*v.z + v.w*v.w;
    #pragma unroll
    for (int off = 16; off; off >>= 1) ss += __shfl_xor_sync(0xffffffffu, ss, off);
    float r = rsqrtf(ss * (1.0f / DVq) + 1e-6f);
    float4 wv = ((const float4*)w)[lane];
    float4 g = gp[lane];
    float4 ov = make_float4(v.x*r*wv.x*siluf(g.x), v.y*r*wv.y*siluf(g.y),
                            v.z*r*wv.z*siluf(g.z), v.w*r*wv.w*siluf(g.w));
    ull hi, lo; split4(ov, hi, lo);
    __nv_bfloat16* rb = outb + (size_t)m * 6144 + hh * DVq + lane * 4;
    *(ull*)rb = hi;
    *(ull*)(rb + 2048) = lo;
    *(ull*)(rb + 4096) = hi;
}

// ---------------- gated delta-rule scan (conflict-free ring + f32x2) ---------
// ring slot layout (floats): k chunks at sub*20 (0,20,40,60); q at 80+sub*20;
// v at 160..223; decay 224; beta 225. RSTRIDE=228.
#define RSTRIDE 228
__global__ void __launch_bounds__(256)
scan_kernel(const float* __restrict__ q, const float* __restrict__ k,
            const float* __restrict__ v, const float* __restrict__ dec,
            const float* __restrict__ bt, float* __restrict__ o) {
    __shared__ alignas(16) float ring[16 * RSTRIDE];
    int half = blockIdx.x & 1;
    int bh = blockIdx.x >> 1;
    int b = bh >> 4, h = bh & 15;
    int tid = threadIdx.x;
    int colL = tid >> 2, sub = tid & 3;
    int col = half * 64 + colL;

    size_t rowBase = (size_t)b * Tq;
    const float* kb = k + rowBase * Dq + h * DKq;
    const float* qb = q + rowBase * Dq + h * DKq;
    const float* vb = v + rowBase * VDq + h * DVq + half * 64;
    const float* db = dec + rowBase * Hq + h;
    const float* bb = bt + rowBase * Hq + h;
    float* ob = o + rowBase * VDq + h * DVq + col;

    uint32_t ringU = smem_u32(ring);

    auto fill = [&](int hf, int blk) {
        #pragma unroll
        for (int rep = 0; rep < 2; rep++) {
            int idx = tid + rep * 256;
            if (idx < 400) {
                int sid = idx / 50, slot = idx % 50;
                int t = blk * 8 + sid;
                uint32_t sb = ringU + ((hf * 8 + sid) * RSTRIDE) * 4;
                if (slot < 16) {
                    int ch = slot >> 2, i = slot & 3;
                    CP16(sb + (ch * 20 + i * 4) * 4,      kb + (size_t)t * Dq + ch * 16 + i * 4);
                } else if (slot < 32) {
                    int s2 = slot - 16, ch = s2 >> 2, i = s2 & 3;
                    CP16(sb + (80 + ch * 20 + i * 4) * 4, qb + (size_t)t * Dq + ch * 16 + i * 4);
                } else if (slot < 48) {
                    CP16(sb + (160 + (slot - 32) * 4) * 4, vb + (size_t)t * VDq + (slot - 32) * 4);
                } else if (slot == 48) {
                    CP4(sb + 224 * 4, db + (size_t)t * Hq);
                } else {
                    CP4(sb + 225 * 4, bb + (size_t)t * Hq);
                }
            }
        }
        CPCOMMIT();
    };

    ull S[8];
    #pragma unroll
    for (int p = 0; p < 8; p++) S[p] = 0ull;

    fill(0, 0);
    fill(1, 1);

    for (int blk = 0; blk < 256; blk++) {
        CPWAIT1();
        __syncthreads();
        int hf = blk & 1;
        #pragma unroll 1
        for (int j = 0; j < 8; j++) {
            const float* st = &ring[(hf * 8 + j) * RSTRIDE];
            const ull* kp = (const ull*)(st + sub * 20);
            const ull* qp = (const ull*)(st + 80 + sub * 20);
            float vt = st[160 + colL];
            float decay = st[224], bet = st[225];
            ull dpk = dup2(decay);
            ull kr[8], qr[8];
            #pragma unroll
            for (int p = 0; p < 8; p++) { kr[p] = kp[p]; qr[p] = qp[p]; }
            ull vpp = 0ull;
            #pragma unroll
            for (int p = 0; p < 8; p++) {
                S[p] = mul2(S[p], dpk);
                vpp = ffma2(kr[p], S[p], vpp);
            }
            float2 vpf = unpk(vpp);
            float vp = vpf.x + vpf.y;
            vp += __shfl_xor_sync(0xffffffffu, vp, 1);
            vp += __shfl_xor_sync(0xffffffffu, vp, 2);
            float u = bet * (vt - vp);
            ull up = dup2(u);
            ull opp = 0ull;
            #pragma unroll
            for (int p = 0; p < 8; p++) {
                S[p] = ffma2(kr[p], up, S[p]);
                opp = ffma2(qr[p], S[p], opp);
            }
            float2 otf = unpk(opp);
            float ot = otf.x + otf.y;
            ot += __shfl_xor_sync(0xffffffffu, ot, 1);
            ot += __shfl_xor_sync(0xffffffffu, ot, 2);
            if (sub == 0) ob[(size_t)(blk * 8 + j) * VDq] = ot;
        }
        __syncthreads();
        if (blk + 2 < 256) fill(hf, blk + 2);
        else CPCOMMIT();
    }
}

// ---------------- host orchestration -----------------------------------------
static inline void launch_gemm(const __nv_bfloat16* A, const __nv_bfloat16* B,
                               const float* R, float* C, int N, int KK, int addR) {
    dim3 grid(N / 128, Mq / 128);
    gemm_tc<<<grid, 256, GSMEM>>>(A, B, R, C, N, KK, addR);
}

extern "C" void kernel_launch(void* const* d_in, const int* in_sizes, int n_in,
                              void* d_out, int out_size) {
    const float* hidden   = (const float*)d_in[0];
    const float* norm_w   = (const float*)d_in[1];
    const float* q_w      = (const float*)d_in[2];
    const float* k_w      = (const float*)d_in[3];
    const float* v_w      = (const float*)d_in[4];
    const float* b_w      = (const float*)d_in[5];
    const float* a_w      = (const float*)d_in[6];
    const float* A_log    = (const float*)d_in[7];
    const float* dt_bias  = (const float*)d_in[8];
    const float* conv_q_w = (const float*)d_in[9];
    const float* conv_k_w = (const float*)d_in[10];
    const float* conv_v_w = (const float*)d_in[11];
    const float* g_wm     = (const float*)d_in[12];
    const float* o_norm_w = (const float*)d_in[13];
    const float* o_w      = (const float*)d_in[14];
    const float* post_w   = (const float*)d_in[15];
    const float* gate_w   = (const float*)d_in[16];
    const float* up_w     = (const float*)d_in[17];
    const float* down_w   = (const float*)d_in[18];
    float* out = (float*)d_out;

    float *p_h, *p_qkvg, *p_q, *p_k, *p_v, *p_bt, *p_gd, *p_o, *p_x, *p_gu;
    __nv_bfloat16 *p_A, *p_Bqkvg, *p_Bo, *p_Bmlp, *p_Bdwn;
    cudaGetSymbolAddress((void**)&p_h, g_h);
    cudaGetSymbolAddress((void**)&p_qkvg, g_qkvg);
    cudaGetSymbolAddress((void**)&p_q, g_q);
    cudaGetSymbolAddress((void**)&p_k, g_k);
    cudaGetSymbolAddress((void**)&p_v, g_v);
    cudaGetSymbolAddress((void**)&p_bt, g_bt);
    cudaGetSymbolAddress((void**)&p_gd, g_gd);
    cudaGetSymbolAddress((void**)&p_o, g_o);
    cudaGetSymbolAddress((void**)&p_x, g_x);
    cudaGetSymbolAddress((void**)&p_gu, g_gu);
    cudaGetSymbolAddress((void**)&p_A, g_Aexp);
    cudaGetSymbolAddress((void**)&p_Bqkvg, g_Bqkvg);
    cudaGetSymbolAddress((void**)&p_Bo, g_Bo);
    cudaGetSymbolAddress((void**)&p_Bmlp, g_Bmlp);
    cudaGetSymbolAddress((void**)&p_Bdwn, g_Bdwn);

    cudaFuncSetAttribute(gemm_tc, cudaFuncAttributeMaxDynamicSharedMemorySize, GSMEM);

    // weight conversion (B'' = [Bh|Bh|Bl], transposed to [N][3K])
    splitT<<<dim3(32, 32), dim3(32, 8)>>>(q_w,    p_Bqkvg,                        1024, 1024);
    splitT<<<dim3(32, 32), dim3(32, 8)>>>(k_w,    p_Bqkvg + (size_t)1024 * 3072,  1024, 1024);
    splitT<<<dim3(64, 32), dim3(32, 8)>>>(v_w,    p_Bqkvg + (size_t)2048 * 3072,  1024, 2048);
    splitT<<<dim3(64, 32), dim3(32, 8)>>>(g_wm,   p_Bqkvg + (size_t)4096 * 3072,  1024, 2048);
    splitT<<<dim3(32, 64), dim3(32, 8)>>>(o_w,    p_Bo,                           2048, 1024);
    splitT<<<dim3(86, 32), dim3(32, 8)>>>(gate_w, p_Bmlp,                         1024, 2752);
    splitT<<<dim3(86, 32), dim3(32, 8)>>>(up_w,   p_Bmlp + (size_t)2752 * 3072,   1024, 2752);
    cudaMemsetAsync(p_Bmlp + (size_t)5504 * 3072, 0, (size_t)128 * 3072 * sizeof(__nv_bfloat16));
    splitT<<<dim3(32, 86), dim3(32, 8)>>>(down_w, p_Bdwn,                         2752, 1024);

    // 1) pre-norm (fp32 for ba_kernel + bf16 split for GEMM)
    rmsnorm_split_kernel<<<Mq, 256>>>(hidden, norm_w, p_h, p_A);
    ba_kernel<<<Mq / 4, 128>>>(p_h, b_w, a_w, A_log, dt_bias, p_bt, p_gd);

    // 2) fused q|k|v|gate projection (N=6144, KK=3072)
    launch_gemm(p_A, p_Bqkvg, nullptr, p_qkvg, 6144, 3072, 0);

    // 3) conv+silu(+l2norm for q/k; q pre-scaled by dk^-0.5)
    conv_l2_kernel<<<(Mq * Hq) / 8, 256>>>(p_qkvg,        6144, conv_q_w, p_q, 0.125f);
    conv_l2_kernel<<<(Mq * Hq) / 8, 256>>>(p_qkvg + 1024, 6144, conv_k_w, p_k, 1.0f);
    conv_silu_kernel<<<(int)(((size_t)Mq * 2048 + 255) / 256), 256>>>(p_qkvg + 2048, 6144, conv_v_w, p_v, 2048);

    // 4) scan
    scan_kernel<<<Bq * Hq * 2, 256>>>(p_q, p_k, p_v, p_gd, p_bt, p_o);

    // 5) gated per-head RMSNorm -> bf16 split
    gated_split_kernel<<<(Mq * Hq) / 8, 256>>>(p_o, o_norm_w, p_qkvg + 4096, 6144, p_A);

    // 6) output projection + residual
    launch_gemm(p_A, p_Bo, hidden, p_x, 1024, 6144, 1);

    // 7) post norm -> bf16 split only
    rmsnorm_split_kernel<<<Mq, 256>>>(p_x, post_w, nullptr, p_A);

    // 8) MLP
    launch_gemm(p_A, p_Bmlp, nullptr, p_gu, FFp, 3072, 0);
    act_split<<<(int)(((size_t)Mq * FFq + 255) / 256), 256>>>(p_gu, p_A);
    launch_gemm(p_A, p_Bdwn, p_x, out, 1024, 8256, 1);
}

// round 9
// speedup vs baseline: 2.7863x; 1.0726x over previous
#include <cuda_runtime.h>
#include <cuda_bf16.h>
#include <cstdint>

#define Bq 2
#define Tq 2048
#define Dq 1024
#define VDq 2048
#define FFq 2752
#define FFp 5632        // gate|up fused, padded
#define Hq 16
#define DKq 64
#define DVq 128
#define Mq (Bq*Tq)      // 4096

// ---------------- device scratch --------------------------------------------
__device__ float g_h   [Mq*(size_t)Dq];
__device__ float g_qkvg[Mq*(size_t)6144];
__device__ float g_q   [Mq*(size_t)Dq];
__device__ float g_k   [Mq*(size_t)Dq];
__device__ float g_v   [Mq*(size_t)VDq];
__device__ float g_bt  [Mq*(size_t)Hq];
__device__ float g_gd  [Mq*(size_t)Hq];     // exp(g) decay
__device__ float g_o   [Mq*(size_t)VDq];
__device__ float g_x   [Mq*(size_t)Dq];
__device__ float g_gu  [Mq*(size_t)FFp];
__device__ __nv_bfloat16 g_Aexp [Mq*(size_t)8256];
__device__ __nv_bfloat16 g_Bqkvg[(size_t)6144*3072];
__device__ __nv_bfloat16 g_Bo   [(size_t)1024*6144];
__device__ __nv_bfloat16 g_Bmlp [(size_t)FFp*3072];
__device__ __nv_bfloat16 g_Bdwn [(size_t)1024*8256];

// ---------------- PTX helpers ------------------------------------------------
__device__ __forceinline__ uint32_t smem_u32(const void* p) {
    uint32_t a;
    asm("{ .reg .u64 t; cvta.to.shared.u64 t, %1; cvt.u32.u64 %0, t; }" : "=r"(a) : "l"(p));
    return a;
}
typedef unsigned long long ull;
__device__ __forceinline__ ull ffma2(ull a, ull b, ull c) {
    ull d; asm("fma.rn.f32x2 %0,%1,%2,%3;" : "=l"(d) : "l"(a), "l"(b), "l"(c)); return d;
}
__device__ __forceinline__ ull mul2(ull a, ull b) {
    ull d; asm("mul.rn.f32x2 %0,%1,%2;" : "=l"(d) : "l"(a), "l"(b)); return d;
}
__device__ __forceinline__ ull dup2(float x) {
    ull r; asm("mov.b64 %0, {%1,%1};" : "=l"(r) : "f"(x)); return r;
}
__device__ __forceinline__ float2 unpk(ull a) {
    float2 f; asm("mov.b64 {%0,%1}, %2;" : "=f"(f.x), "=f"(f.y) : "l"(a)); return f;
}
__device__ __forceinline__ float siluf(float x) { return x / (1.0f + __expf(-x)); }

__device__ __forceinline__ void split4(float4 v, ull& hi, ull& lo) {
    __nv_bfloat16 h0 = __float2bfloat16(v.x), h1 = __float2bfloat16(v.y),
                  h2 = __float2bfloat16(v.z), h3 = __float2bfloat16(v.w);
    __nv_bfloat16 l0 = __float2bfloat16(v.x - __bfloat162float(h0));
    __nv_bfloat16 l1 = __float2bfloat16(v.y - __bfloat162float(h1));
    __nv_bfloat16 l2 = __float2bfloat16(v.z - __bfloat162float(h2));
    __nv_bfloat16 l3 = __float2bfloat16(v.w - __bfloat162float(h3));
    ushort4 hu = make_ushort4(__bfloat16_as_ushort(h0), __bfloat16_as_ushort(h1),
                              __bfloat16_as_ushort(h2), __bfloat16_as_ushort(h3));
    ushort4 lu = make_ushort4(__bfloat16_as_ushort(l0), __bfloat16_as_ushort(l1),
                              __bfloat16_as_ushort(l2), __bfloat16_as_ushort(l3));
    hi = *(ull*)&hu; lo = *(ull*)&lu;
}

#define SWZ(o) ((o) ^ (((o) >> 3) & 0x70))
#define CP16(d, s) asm volatile("cp.async.cg.shared.global [%0], [%1], 16;" :: "r"(d), "l"(s) : "memory")
#define CP4(d, s)  asm volatile("cp.async.ca.shared.global [%0], [%1], 4;"  :: "r"(d), "l"(s) : "memory")
#define CPCOMMIT() asm volatile("cp.async.commit_group;" ::: "memory")
#define CPWAIT1()  asm volatile("cp.async.wait_group 1;" ::: "memory")

#define LDMX4(r0,r1,r2,r3,addr) \
    asm volatile("ldmatrix.sync.aligned.m8n8.x4.shared.b16 {%0,%1,%2,%3}, [%4];" \
                 : "=r"(r0), "=r"(r1), "=r"(r2), "=r"(r3) : "r"(addr))

#define MMA16816(c, a, b) \
    asm volatile("mma.sync.aligned.m16n8k16.row.col.f32.bf16.bf16.f32 " \
                 "{%0,%1,%2,%3}, {%4,%5,%6,%7}, {%8,%9}, {%0,%1,%2,%3};" \
                 : "+f"((c)[0]), "+f"((c)[1]), "+f"((c)[2]), "+f"((c)[3]) \
                 : "r"((a)[0]), "r"((a)[1]), "r"((a)[2]), "r"((a)[3]), \
                   "r"((b)[0]), "r"((b)[1]))

// ---------------- weight split/transpose -------------------------------------
__global__ void splitT(const float* __restrict__ W, __nv_bfloat16* __restrict__ out, int K, int N) {
    // W[K][N] -> out[N][3K] = [Bh|Bh|Bl]
    __shared__ float tile[32][33];
    int n0 = blockIdx.x * 32, k0 = blockIdx.y * 32;
    for (int r = threadIdx.y; r < 32; r += 8)
        tile[r][threadIdx.x] = W[(size_t)(k0 + r) * N + n0 + threadIdx.x];
    __syncthreads();
    for (int r = threadIdx.y; r < 32; r += 8) {
        int n = n0 + r, kk = k0 + threadIdx.x;
        float x = tile[threadIdx.x][r];
        __nv_bfloat16 hi = __float2bfloat16(x);
        __nv_bfloat16 lo = __float2bfloat16(x - __bfloat162float(hi));
        __nv_bfloat16* orow = out + (size_t)n * (3 * K);
        orow[kk] = hi; orow[K + kk] = hi; orow[2 * K + kk] = lo;
    }
}

__global__ void act_split(const float* __restrict__ gu, __nv_bfloat16* __restrict__ out) {
    size_t i = (size_t)blockIdx.x * 256 + threadIdx.x;
    if (i >= (size_t)Mq * FFq) return;
    size_t m = i / FFq; int kk = (int)(i % FFq);
    float g = gu[m * FFp + kk], u = gu[m * FFp + FFq + kk];
    float a = siluf(g) * u;
    __nv_bfloat16 hi = __float2bfloat16(a);
    __nv_bfloat16 lo = __float2bfloat16(a - __bfloat162float(hi));
    __nv_bfloat16* r = out + m * (size_t)(3 * FFq);
    r[kk] = hi; r[FFq + kk] = lo; r[2 * FFq + kk] = hi;
}

// ---------------- bf16 mma.sync GEMM, 128x256 CTA tile, warp 64x64 ------------
#define STG_A 16384
#define STG_B 32768
#define NSTAGE 3
#define GSMEM (1024 + NSTAGE*(STG_A + STG_B))

__global__ void __launch_bounds__(256, 1)
gemm_tc(const __nv_bfloat16* __restrict__ A, const __nv_bfloat16* __restrict__ B,
        const float* __restrict__ R, float* __restrict__ C, int N, int KK, int addR) {
    extern __shared__ char dsm[];
    uint32_t base = smem_u32(dsm);
    uint32_t uA = (base + 1023) & ~1023u;
    uint32_t uB = uA + NSTAGE * STG_A;

    const int tid = threadIdx.x;
    const int wid = tid >> 5, lane = tid & 31;
    const int bm = blockIdx.y * 128;
    const int bn = blockIdx.x * 256;
    const int wm = (wid & 1) * 64;
    const int wn = (wid >> 1) * 64;
    const int nslab = KK >> 6;

    auto fill = [&](int stg, int slab) {
        int k0 = slab << 6;
        const __nv_bfloat16* Ab = A + (size_t)bm * KK + k0;
        const __nv_bfloat16* Bb = B + (size_t)bn * KK + k0;
        uint32_t sA = uA + stg * STG_A, sB = uB + stg * STG_B;
        #pragma unroll
        for (int i = 0; i < 12; i++) {
            int id = tid + (i << 8);
            if (id < 1024) {
                int row = id >> 3, c = id & 7;
                CP16(sA + SWZ(row * 128 + c * 16), Ab + (size_t)row * KK + c * 8);
            } else {
                int bid = id - 1024;
                int row = bid >> 3, c = bid & 7;
                CP16(sB + SWZ(row * 128 + c * 16), Bb + (size_t)row * KK + c * 8);
            }
        }
        CPCOMMIT();
    };

    float acc[4][8][4];
    #pragma unroll
    for (int mt = 0; mt < 4; mt++)
        #pragma unroll
        for (int nt = 0; nt < 8; nt++)
            #pragma unroll
            for (int j = 0; j < 4; j++) acc[mt][nt][j] = 0.f;

    fill(0, 0);
    if (nslab > 1) fill(1, 1); else CPCOMMIT();

    const int a_row = (lane & 15);
    const int a_sel = (lane >> 4);
    const int b_row = (lane & 7) + ((lane >> 4) << 3);
    const int b_sel = (lane >> 3) & 1;

    for (int s = 0; s < nslab; s++) {
        CPWAIT1();
        __syncthreads();
        uint32_t sA = uA + (s % NSTAGE) * STG_A;
        uint32_t sB = uB + (s % NSTAGE) * STG_B;
        #pragma unroll
        for (int ks = 0; ks < 4; ks++) {
            uint32_t a[4][4], b[8][2];
            #pragma unroll
            for (int mt = 0; mt < 4; mt++) {
                uint32_t addr = sA + SWZ((wm + mt * 16 + a_row) * 128 + (ks * 2 + a_sel) * 16);
                LDMX4(a[mt][0], a[mt][1], a[mt][2], a[mt][3], addr);
            }
            #pragma unroll
            for (int bt = 0; bt < 4; bt++) {
                uint32_t addr = sB + SWZ((wn + bt * 16 + b_row) * 128 + (ks * 2 + b_sel) * 16);
                LDMX4(b[bt*2][0], b[bt*2][1], b[bt*2+1][0], b[bt*2+1][1], addr);
            }
            #pragma unroll
            for (int mt = 0; mt < 4; mt++)
                #pragma unroll
                for (int nt = 0; nt < 8; nt++)
                    MMA16816(acc[mt][nt], a[mt], b[nt]);
        }
        __syncthreads();
        if (s + 2 < nslab) fill((s + 2) % NSTAGE, s + 2);
        else CPCOMMIT();
    }

    #pragma unroll
    for (int mt = 0; mt < 4; mt++) {
        #pragma unroll
        for (int h = 0; h < 2; h++) {
            int row = bm + wm + mt * 16 + (lane >> 2) + h * 8;
            float* crow = C + (size_t)row * N + bn + wn + 2 * (lane & 3);
            const float* rrow = addR ? (R + (size_t)row * N + bn + wn + 2 * (lane & 3)) : nullptr;
            #pragma unroll
            for (int nt = 0; nt < 8; nt++) {
                float2 ov = make_float2(acc[mt][nt][h*2], acc[mt][nt][h*2+1]);
                if (addR) {
                    float2 rv = *(const float2*)(rrow + nt * 8);
                    ov.x += rv.x; ov.y += rv.y;
                }
                *(float2*)(crow + nt * 8) = ov;
            }
        }
    }
}

// ---------------- fused RMSNorm -> (optional f32) + bf16 split ---------------
__global__ void rmsnorm_split_kernel(const float* __restrict__ x, const float* __restrict__ w,
                                     float* __restrict__ outf,
                                     __nv_bfloat16* __restrict__ outb) {
    int row = blockIdx.x;
    float4 v = ((const float4*)(x + (size_t)row * Dq))[threadIdx.x];
    float ss = v.x*v.x + v.y*v.y + v.z*v.z + v.w*v.w;
    #pragma unroll
    for (int o = 16; o; o >>= 1) ss += __shfl_xor_sync(0xffffffffu, ss, o);
    __shared__ float red[8];
    int wd = threadIdx.x >> 5, ln = threadIdx.x & 31;
    if (ln == 0) red[wd] = ss;
    __syncthreads();
    float tot = red[0]+red[1]+red[2]+red[3]+red[4]+red[5]+red[6]+red[7];
    float r = rsqrtf(tot * (1.0f / Dq) + 1e-6f);
    float4 wv = ((const float4*)w)[threadIdx.x];
    float4 ov = make_float4(v.x*r*wv.x, v.y*r*wv.y, v.z*r*wv.z, v.w*r*wv.w);
    if (outf) ((float4*)(outf + (size_t)row * Dq))[threadIdx.x] = ov;
    ull hi, lo; split4(ov, hi, lo);
    ull* rb = (ull*)(outb + (size_t)row * 3072 + threadIdx.x * 4);
    rb[0] = hi;
    *(ull*)((__nv_bfloat16*)rb + 1024) = lo;
    *(ull*)((__nv_bfloat16*)rb + 2048) = hi;
}

// ---------------- fused conv+silu+l2norm for q/k ------------------------------
__global__ void conv_l2_kernel(const float* __restrict__ in, int stride,
                               const float* __restrict__ w,
                               float* __restrict__ out, float scale) {
    int vec = blockIdx.x * 8 + (threadIdx.x >> 5);   // bt*16 + h
    int lane = threadIdx.x & 31;
    int bt = vec >> 4, h = vec & 15;
    int t = bt & (Tq - 1);
    int c = h * 64 + lane * 2;
    const float* p = in + (size_t)bt * stride + c;
    float2 x0 = *(const float2*)p;
    float2 x1 = (t >= 1) ? *(const float2*)(p - stride)     : make_float2(0.f, 0.f);
    float2 x2 = (t >= 2) ? *(const float2*)(p - 2 * stride) : make_float2(0.f, 0.f);
    float2 x3 = (t >= 3) ? *(const float2*)(p - 3 * stride) : make_float2(0.f, 0.f);
    float4 w0 = ((const float4*)w)[c];
    float4 w1 = ((const float4*)w)[c + 1];
    float a0 = w0.w*x0.x + w0.z*x1.x + w0.y*x2.x + w0.x*x3.x;
    float a1 = w1.w*x0.y + w1.z*x1.y + w1.y*x2.y + w1.x*x3.y;
    a0 = siluf(a0); a1 = siluf(a1);
    float ss = a0*a0 + a1*a1;
    #pragma unroll
    for (int o = 16; o; o >>= 1) ss += __shfl_xor_sync(0xffffffffu, ss, o);
    float r = rsqrtf(ss + 1e-6f) * scale;
    *(float2*)(out + (size_t)bt * Dq + c) = make_float2(a0 * r, a1 * r);
}

// ---------------- conv+silu for v (elementwise) -------------------------------
__global__ void conv_silu_kernel(const float* __restrict__ in, int stride,
                                 const float* __restrict__ w,
                                 float* __restrict__ out, int C) {
    size_t idx = (size_t)blockIdx.x * 256 + threadIdx.x;
    if (idx >= (size_t)Mq * C) return;
    int c = (int)(idx % C);
    size_t bt = idx / C;
    int t = (int)(bt % Tq);
    const float* p = in + bt * (size_t)stride + c;
    float4 wv = ((const float4*)w)[c];
    float acc = wv.w * p[0];
    if (t >= 1) acc += wv.z * p[-(ptrdiff_t)stride];
    if (t >= 2) acc += wv.y * p[-2 * (ptrdiff_t)stride];
    if (t >= 3) acc += wv.x * p[-3 * (ptrdiff_t)stride];
    out[idx] = siluf(acc);
}

__global__ void ba_kernel(const float* __restrict__ h, const float* __restrict__ b_w,
                          const float* __restrict__ a_w, const float* __restrict__ A_log,
                          const float* __restrict__ dt_bias,
                          float* __restrict__ beta, float* __restrict__ dec) {
    int row = blockIdx.x * 4 + (threadIdx.x >> 5);
    int lane = threadIdx.x & 31;
    int c = lane & 15;
    const float* W = (lane < 16) ? b_w : a_w;
    const float* hr = h + (size_t)row * Dq;
    float a0 = 0.f, a1 = 0.f, a2 = 0.f, a3 = 0.f;
    for (int kk = 0; kk < Dq; kk += 4) {
        a0 += hr[kk+0] * W[(kk+0)*Hq + c];
        a1 += hr[kk+1] * W[(kk+1)*Hq + c];
        a2 += hr[kk+2] * W[(kk+2)*Hq + c];
        a3 += hr[kk+3] * W[(kk+3)*Hq + c];
    }
    float acc = (a0 + a1) + (a2 + a3);
    if (lane < 16) {
        beta[(size_t)row * Hq + c] = 1.0f / (1.0f + __expf(-acc));
    } else {
        float xv = acc + dt_bias[c];
        float sp = fmaxf(xv, 0.f) + log1pf(__expf(-fabsf(xv)));
        dec[(size_t)row * Hq + c] = __expf(-__expf(A_log[c]) * sp);
    }
}

// ---------------- fused gated RMSNorm -> bf16 split ---------------------------
__global__ void gated_split_kernel(const float* __restrict__ o, const float* __restrict__ w,
                                   const float* __restrict__ gate, int gstride,
                                   __nv_bfloat16* __restrict__ outb) {
    int vec = blockIdx.x * 8 + (threadIdx.x >> 5);
    int lane = threadIdx.x & 31;
    int m = vec >> 4, hh = vec & 15;
    const float4* op = (const float4*)(o + (size_t)vec * DVq);
    const float4* gp = (const float4*)(gate + (size_t)m * gstride + hh * DVq);
    float4 v = op[lane];
    float ss = v.x*v.x + v.y*v.y + v.z*v.z + v.w*v.w;
    #pragma unroll
    for (int off = 16; off; off >>= 1) ss += __shfl_xor_sync(0xffffffffu, ss, off);
    float r = rsqrtf(ss * (1.0f / DVq) + 1e-6f);
    float4 wv = ((const float4*)w)[lane];
    float4 g = gp[lane];
    float4 ov = make_float4(v.x*r*wv.x*siluf(g.x), v.y*r*wv.y*siluf(g.y),
                            v.z*r*wv.z*siluf(g.z), v.w*r*wv.w*siluf(g.w));
    ull hi, lo; split4(ov, hi, lo);
    __nv_bfloat16* rb = outb + (size_t)m * 6144 + hh * DVq + lane * 4;
    *(ull*)rb = hi;
    *(ull*)(rb + 2048) = lo;
    *(ull*)(rb + 4096) = hi;
}

// ---------------- gated delta-rule scan (conflict-free ring + f32x2) ---------
#define RSTRIDE 228
__global__ void __launch_bounds__(256)
scan_kernel(const float* __restrict__ q, const float* __restrict__ k,
            const float* __restrict__ v, const float* __restrict__ dec,
            const float* __restrict__ bt, float* __restrict__ o) {
    __shared__ alignas(16) float ring[16 * RSTRIDE];
    int half = blockIdx.x & 1;
    int bh = blockIdx.x >> 1;
    int b = bh >> 4, h = bh & 15;
    int tid = threadIdx.x;
    int colL = tid >> 2, sub = tid & 3;
    int col = half * 64 + colL;

    size_t rowBase = (size_t)b * Tq;
    const float* kb = k + rowBase * Dq + h * DKq;
    const float* qb = q + rowBase * Dq + h * DKq;
    const float* vb = v + rowBase * VDq + h * DVq + half * 64;
    const float* db = dec + rowBase * Hq + h;
    const float* bb = bt + rowBase * Hq + h;
    float* ob = o + rowBase * VDq + h * DVq + col;

    uint32_t ringU = smem_u32(ring);

    auto fill = [&](int hf, int blk) {
        #pragma unroll
        for (int rep = 0; rep < 2; rep++) {
            int idx = tid + rep * 256;
            if (idx < 400) {
                int sid = idx / 50, slot = idx % 50;
                int t = blk * 8 + sid;
                uint32_t sb = ringU + ((hf * 8 + sid) * RSTRIDE) * 4;
                if (slot < 16) {
                    int ch = slot >> 2, i = slot & 3;
                    CP16(sb + (ch * 20 + i * 4) * 4,      kb + (size_t)t * Dq + ch * 16 + i * 4);
                } else if (slot < 32) {
                    int s2 = slot - 16, ch = s2 >> 2, i = s2 & 3;
                    CP16(sb + (80 + ch * 20 + i * 4) * 4, qb + (size_t)t * Dq + ch * 16 + i * 4);
                } else if (slot < 48) {
                    CP16(sb + (160 + (slot - 32) * 4) * 4, vb + (size_t)t * VDq + (slot - 32) * 4);
                } else if (slot == 48) {
                    CP4(sb + 224 * 4, db + (size_t)t * Hq);
                } else {
                    CP4(sb + 225 * 4, bb + (size_t)t * Hq);
                }
            }
        }
        CPCOMMIT();
    };

    ull S[8];
    #pragma unroll
    for (int p = 0; p < 8; p++) S[p] = 0ull;

    fill(0, 0);
    fill(1, 1);

    for (int blk = 0; blk < 256; blk++) {
        CPWAIT1();
        __syncthreads();
        int hf = blk & 1;
        #pragma unroll 1
        for (int j = 0; j < 8; j++) {
            const float* st = &ring[(hf * 8 + j) * RSTRIDE];
            const ull* kp = (const ull*)(st + sub * 20);
            const ull* qp = (const ull*)(st + 80 + sub * 20);
            float vt = st[160 + colL];
            float decay = st[224], bet = st[225];
            ull dpk = dup2(decay);
            ull kr[8], qr[8];
            #pragma unroll
            for (int p = 0; p < 8; p++) { kr[p] = kp[p]; qr[p] = qp[p]; }
            ull vpa = 0ull, vpb = 0ull;
            #pragma unroll
            for (int p = 0; p < 8; p += 2) {
                S[p]   = mul2(S[p],   dpk);
                S[p+1] = mul2(S[p+1], dpk);
                vpa = ffma2(kr[p],   S[p],   vpa);
                vpb = ffma2(kr[p+1], S[p+1], vpb);
            }
            float2 vpf = unpk(vpa), vpg = unpk(vpb);
            float vp = (vpf.x + vpf.y) + (vpg.x + vpg.y);
            vp += __shfl_xor_sync(0xffffffffu, vp, 1);
            vp += __shfl_xor_sync(0xffffffffu, vp, 2);
            float u = bet * (vt - vp);
            ull up = dup2(u);
            ull opa = 0ull, opb = 0ull;
            #pragma unroll
            for (int p = 0; p < 8; p += 2) {
                S[p]   = ffma2(kr[p],   up, S[p]);
                S[p+1] = ffma2(kr[p+1], up, S[p+1]);
                opa = ffma2(qr[p],   S[p],   opa);
                opb = ffma2(qr[p+1], S[p+1], opb);
            }
            float2 otf = unpk(opa), otg = unpk(opb);
            float ot = (otf.x + otf.y) + (otg.x + otg.y);
            ot += __shfl_xor_sync(0xffffffffu, ot, 1);
            ot += __shfl_xor_sync(0xffffffffu, ot, 2);
            if (sub == 0) ob[(size_t)(blk * 8 + j) * VDq] = ot;
        }
        __syncthreads();
        if (blk + 2 < 256) fill(hf, blk + 2);
        else CPCOMMIT();
    }
}

// ---------------- host orchestration -----------------------------------------
static inline void launch_gemm(const __nv_bfloat16* A, const __nv_bfloat16* B,
                               const float* R, float* C, int N, int KK, int addR) {
    dim3 grid(N / 256, Mq / 128);
    gemm_tc<<<grid, 256, GSMEM>>>(A, B, R, C, N, KK, addR);
}

extern "C" void kernel_launch(void* const* d_in, const int* in_sizes, int n_in,
                              void* d_out, int out_size) {
    const float* hidden   = (const float*)d_in[0];
    const float* norm_w   = (const float*)d_in[1];
    const float* q_w      = (const float*)d_in[2];
    const float* k_w      = (const float*)d_in[3];
    const float* v_w      = (const float*)d_in[4];
    const float* b_w      = (const float*)d_in[5];
    const float* a_w      = (const float*)d_in[6];
    const float* A_log    = (const float*)d_in[7];
    const float* dt_bias  = (const float*)d_in[8];
    const float* conv_q_w = (const float*)d_in[9];
    const float* conv_k_w = (const float*)d_in[10];
    const float* conv_v_w = (const float*)d_in[11];
    const float* g_wm     = (const float*)d_in[12];
    const float* o_norm_w = (const float*)d_in[13];
    const float* o_w      = (const float*)d_in[14];
    const float* post_w   = (const float*)d_in[15];
    const float* gate_w   = (const float*)d_in[16];
    const float* up_w     = (const float*)d_in[17];
    const float* down_w   = (const float*)d_in[18];
    float* out = (float*)d_out;

    float *p_h, *p_qkvg, *p_q, *p_k, *p_v, *p_bt, *p_gd, *p_o, *p_x, *p_gu;
    __nv_bfloat16 *p_A, *p_Bqkvg, *p_Bo, *p_Bmlp, *p_Bdwn;
    cudaGetSymbolAddress((void**)&p_h, g_h);
    cudaGetSymbolAddress((void**)&p_qkvg, g_qkvg);
    cudaGetSymbolAddress((void**)&p_q, g_q);
    cudaGetSymbolAddress((void**)&p_k, g_k);
    cudaGetSymbolAddress((void**)&p_v, g_v);
    cudaGetSymbolAddress((void**)&p_bt, g_bt);
    cudaGetSymbolAddress((void**)&p_gd, g_gd);
    cudaGetSymbolAddress((void**)&p_o, g_o);
    cudaGetSymbolAddress((void**)&p_x, g_x);
    cudaGetSymbolAddress((void**)&p_gu, g_gu);
    cudaGetSymbolAddress((void**)&p_A, g_Aexp);
    cudaGetSymbolAddress((void**)&p_Bqkvg, g_Bqkvg);
    cudaGetSymbolAddress((void**)&p_Bo, g_Bo);
    cudaGetSymbolAddress((void**)&p_Bmlp, g_Bmlp);
    cudaGetSymbolAddress((void**)&p_Bdwn, g_Bdwn);

    cudaFuncSetAttribute(gemm_tc, cudaFuncAttributeMaxDynamicSharedMemorySize, GSMEM);

    // weight conversion (B'' = [Bh|Bh|Bl], transposed to [N][3K])
    splitT<<<dim3(32, 32), dim3(32, 8)>>>(q_w,    p_Bqkvg,                        1024, 1024);
    splitT<<<dim3(32, 32), dim3(32, 8)>>>(k_w,    p_Bqkvg + (size_t)1024 * 3072,  1024, 1024);
    splitT<<<dim3(64, 32), dim3(32, 8)>>>(v_w,    p_Bqkvg + (size_t)2048 * 3072,  1024, 2048);
    splitT<<<dim3(64, 32), dim3(32, 8)>>>(g_wm,   p_Bqkvg + (size_t)4096 * 3072,  1024, 2048);
    splitT<<<dim3(32, 64), dim3(32, 8)>>>(o_w,    p_Bo,                           2048, 1024);
    splitT<<<dim3(86, 32), dim3(32, 8)>>>(gate_w, p_Bmlp,                         1024, 2752);
    splitT<<<dim3(86, 32), dim3(32, 8)>>>(up_w,   p_Bmlp + (size_t)2752 * 3072,   1024, 2752);
    cudaMemsetAsync(p_Bmlp + (size_t)5504 * 3072, 0, (size_t)128 * 3072 * sizeof(__nv_bfloat16));
    splitT<<<dim3(32, 86), dim3(32, 8)>>>(down_w, p_Bdwn,                         2752, 1024);

    // 1) pre-norm (fp32 for ba_kernel + bf16 split for GEMM)
    rmsnorm_split_kernel<<<Mq, 256>>>(hidden, norm_w, p_h, p_A);
    ba_kernel<<<Mq / 4, 128>>>(p_h, b_w, a_w, A_log, dt_bias, p_bt, p_gd);

    // 2) fused q|k|v|gate projection (N=6144, KK=3072)
    launch_gemm(p_A, p_Bqkvg, nullptr, p_qkvg, 6144, 3072, 0);

    // 3) conv+silu(+l2norm for q/k; q pre-scaled by dk^-0.5)
    conv_l2_kernel<<<(Mq * Hq) / 8, 256>>>(p_qkvg,        6144, conv_q_w, p_q, 0.125f);
    conv_l2_kernel<<<(Mq * Hq) / 8, 256>>>(p_qkvg + 1024, 6144, conv_k_w, p_k, 1.0f);
    conv_silu_kernel<<<(int)(((size_t)Mq * 2048 + 255) / 256), 256>>>(p_qkvg + 2048, 6144, conv_v_w, p_v, 2048);

    // 4) scan
    scan_kernel<<<Bq * Hq * 2, 256>>>(p_q, p_k, p_v, p_gd, p_bt, p_o);

    // 5) gated per-head RMSNorm -> bf16 split
    gated_split_kernel<<<(Mq * Hq) / 8, 256>>>(p_o, o_norm_w, p_qkvg + 4096, 6144, p_A);

    // 6) output projection + residual
    launch_gemm(p_A, p_Bo, hidden, p_x, 1024, 6144, 1);

    // 7) post norm -> bf16 split only
    rmsnorm_split_kernel<<<Mq, 256>>>(p_x, post_w, nullptr, p_A);

    // 8) MLP
    launch_gemm(p_A, p_Bmlp, nullptr, p_gu, FFp, 3072, 0);
    act_split<<<(int)(((size_t)Mq * FFq + 255) / 256), 256>>>(p_gu, p_A);
    launch_gemm(p_A, p_Bdwn, p_x, out, 1024, 8256, 1);
}

// round 10
// speedup vs baseline: 2.9296x; 1.0514x over previous
#include <cuda_runtime.h>
#include <cuda_bf16.h>
#include <cstdint>

#define Bq 2
#define Tq 2048
#define Dq 1024
#define VDq 2048
#define FFq 2752
#define FFp 5632        // gate|up fused, padded
#define Hq 16
#define DKq 64
#define DVq 128
#define Mq (Bq*Tq)      // 4096

// ---------------- device scratch --------------------------------------------
__device__ float g_h   [Mq*(size_t)Dq];
__device__ float g_qkvg[Mq*(size_t)6144];
__device__ float g_q   [Mq*(size_t)Dq];
__device__ float g_k   [Mq*(size_t)Dq];
__device__ float g_v   [Mq*(size_t)VDq];
__device__ float g_bt  [Mq*(size_t)Hq];
__device__ float g_gd  [Mq*(size_t)Hq];     // exp(g) decay
__device__ float g_o   [Mq*(size_t)VDq];
__device__ float g_x   [Mq*(size_t)Dq];
__device__ float g_gu  [Mq*(size_t)FFp];
__device__ __nv_bfloat16 g_Aexp [Mq*(size_t)8256];
__device__ __nv_bfloat16 g_Bqkvg[(size_t)6144*3072];
__device__ __nv_bfloat16 g_Bo   [(size_t)1024*6144];
__device__ __nv_bfloat16 g_Bmlp [(size_t)FFp*3072];
__device__ __nv_bfloat16 g_Bdwn [(size_t)1024*8256];

// ---------------- PTX helpers ------------------------------------------------
__device__ __forceinline__ uint32_t smem_u32(const void* p) {
    uint32_t a;
    asm("{ .reg .u64 t; cvta.to.shared.u64 t, %1; cvt.u32.u64 %0, t; }" : "=r"(a) : "l"(p));
    return a;
}
typedef unsigned long long ull;
__device__ __forceinline__ ull ffma2(ull a, ull b, ull c) {
    ull d; asm("fma.rn.f32x2 %0,%1,%2,%3;" : "=l"(d) : "l"(a), "l"(b), "l"(c)); return d;
}
__device__ __forceinline__ ull mul2(ull a, ull b) {
    ull d; asm("mul.rn.f32x2 %0,%1,%2;" : "=l"(d) : "l"(a), "l"(b)); return d;
}
__device__ __forceinline__ ull dup2(float x) {
    ull r; asm("mov.b64 %0, {%1,%1};" : "=l"(r) : "f"(x)); return r;
}
__device__ __forceinline__ float2 unpk(ull a) {
    float2 f; asm("mov.b64 {%0,%1}, %2;" : "=f"(f.x), "=f"(f.y) : "l"(a)); return f;
}
__device__ __forceinline__ float siluf(float x) { return x / (1.0f + __expf(-x)); }

__device__ __forceinline__ void split4(float4 v, ull& hi, ull& lo) {
    __nv_bfloat16 h0 = __float2bfloat16(v.x), h1 = __float2bfloat16(v.y),
                  h2 = __float2bfloat16(v.z), h3 = __float2bfloat16(v.w);
    __nv_bfloat16 l0 = __float2bfloat16(v.x - __bfloat162float(h0));
    __nv_bfloat16 l1 = __float2bfloat16(v.y - __bfloat162float(h1));
    __nv_bfloat16 l2 = __float2bfloat16(v.z - __bfloat162float(h2));
    __nv_bfloat16 l3 = __float2bfloat16(v.w - __bfloat162float(h3));
    ushort4 hu = make_ushort4(__bfloat16_as_ushort(h0), __bfloat16_as_ushort(h1),
                              __bfloat16_as_ushort(h2), __bfloat16_as_ushort(h3));
    ushort4 lu = make_ushort4(__bfloat16_as_ushort(l0), __bfloat16_as_ushort(l1),
                              __bfloat16_as_ushort(l2), __bfloat16_as_ushort(l3));
    hi = *(ull*)&hu; lo = *(ull*)&lu;
}

#define SWZ(o) ((o) ^ (((o) >> 3) & 0x70))
#define CP16(d, s) asm volatile("cp.async.cg.shared.global [%0], [%1], 16;" :: "r"(d), "l"(s) : "memory")
#define CP4(d, s)  asm volatile("cp.async.ca.shared.global [%0], [%1], 4;"  :: "r"(d), "l"(s) : "memory")
#define CPCOMMIT() asm volatile("cp.async.commit_group;" ::: "memory")
#define CPWAIT1()  asm volatile("cp.async.wait_group 1;" ::: "memory")
#define CPWAIT2()  asm volatile("cp.async.wait_group 2;" ::: "memory")

#define LDMX4(r0,r1,r2,r3,addr) \
    asm volatile("ldmatrix.sync.aligned.m8n8.x4.shared.b16 {%0,%1,%2,%3}, [%4];" \
                 : "=r"(r0), "=r"(r1), "=r"(r2), "=r"(r3) : "r"(addr))

#define MMA16816(c, a, b) \
    asm volatile("mma.sync.aligned.m16n8k16.row.col.f32.bf16.bf16.f32 " \
                 "{%0,%1,%2,%3}, {%4,%5,%6,%7}, {%8,%9}, {%0,%1,%2,%3};" \
                 : "+f"((c)[0]), "+f"((c)[1]), "+f"((c)[2]), "+f"((c)[3]) \
                 : "r"((a)[0]), "r"((a)[1]), "r"((a)[2]), "r"((a)[3]), \
                   "r"((b)[0]), "r"((b)[1]))

// ---------------- weight split/transpose -------------------------------------
__global__ void splitT(const float* __restrict__ W, __nv_bfloat16* __restrict__ out, int K, int N) {
    // W[K][N] -> out[N][3K] = [Bh|Bh|Bl]
    __shared__ float tile[32][33];
    int n0 = blockIdx.x * 32, k0 = blockIdx.y * 32;
    for (int r = threadIdx.y; r < 32; r += 8)
        tile[r][threadIdx.x] = W[(size_t)(k0 + r) * N + n0 + threadIdx.x];
    __syncthreads();
    for (int r = threadIdx.y; r < 32; r += 8) {
        int n = n0 + r, kk = k0 + threadIdx.x;
        float x = tile[threadIdx.x][r];
        __nv_bfloat16 hi = __float2bfloat16(x);
        __nv_bfloat16 lo = __float2bfloat16(x - __bfloat162float(hi));
        __nv_bfloat16* orow = out + (size_t)n * (3 * K);
        orow[kk] = hi; orow[K + kk] = hi; orow[2 * K + kk] = lo;
    }
}

__global__ void act_split(const float* __restrict__ gu, __nv_bfloat16* __restrict__ out) {
    size_t i = (size_t)blockIdx.x * 256 + threadIdx.x;
    if (i >= (size_t)Mq * FFq) return;
    size_t m = i / FFq; int kk = (int)(i % FFq);
    float g = gu[m * FFp + kk], u = gu[m * FFp + FFq + kk];
    float a = siluf(g) * u;
    __nv_bfloat16 hi = __float2bfloat16(a);
    __nv_bfloat16 lo = __float2bfloat16(a - __bfloat162float(hi));
    __nv_bfloat16* r = out + m * (size_t)(3 * FFq);
    r[kk] = hi; r[FFq + kk] = lo; r[2 * FFq + kk] = hi;
}

// ---------------- bf16 mma.sync GEMM, 128x256 CTA tile, warp 64x64 ------------
// 4-stage cp.async pipeline; fill issued BEFORE compute; single barrier/slab.
#define STG_A 16384
#define STG_B 32768
#define NSTAGE 4
#define GSMEM (1024 + NSTAGE*(STG_A + STG_B))

__global__ void __launch_bounds__(256, 1)
gemm_tc(const __nv_bfloat16* __restrict__ A, const __nv_bfloat16* __restrict__ B,
        const float* __restrict__ R, float* __restrict__ C, int N, int KK, int addR) {
    extern __shared__ char dsm[];
    uint32_t base = smem_u32(dsm);
    uint32_t uA = (base + 1023) & ~1023u;
    uint32_t uB = uA + NSTAGE * STG_A;

    const int tid = threadIdx.x;
    const int wid = tid >> 5, lane = tid & 31;
    const int bm = blockIdx.y * 128;
    const int bn = blockIdx.x * 256;
    const int wm = (wid & 1) * 64;
    const int wn = (wid >> 1) * 64;
    const int nslab = KK >> 6;

    auto fill = [&](int stg, int slab) {
        int k0 = slab << 6;
        const __nv_bfloat16* Ab = A + (size_t)bm * KK + k0;
        const __nv_bfloat16* Bb = B + (size_t)bn * KK + k0;
        uint32_t sA = uA + stg * STG_A, sB = uB + stg * STG_B;
        #pragma unroll
        for (int i = 0; i < 12; i++) {
            int id = tid + (i << 8);
            if (id < 1024) {
                int row = id >> 3, c = id & 7;
                CP16(sA + SWZ(row * 128 + c * 16), Ab + (size_t)row * KK + c * 8);
            } else {
                int bid = id - 1024;
                int row = bid >> 3, c = bid & 7;
                CP16(sB + SWZ(row * 128 + c * 16), Bb + (size_t)row * KK + c * 8);
            }
        }
        CPCOMMIT();
    };

    float acc[4][8][4];
    #pragma unroll
    for (int mt = 0; mt < 4; mt++)
        #pragma unroll
        for (int nt = 0; nt < 8; nt++)
            #pragma unroll
            for (int j = 0; j < 4; j++) acc[mt][nt][j] = 0.f;

    fill(0, 0);
    if (nslab > 1) fill(1, 1); else CPCOMMIT();
    if (nslab > 2) fill(2, 2); else CPCOMMIT();

    const int a_row = (lane & 15);
    const int a_sel = (lane >> 4);
    const int b_row = (lane & 7) + ((lane >> 4) << 3);
    const int b_sel = (lane >> 3) & 1;

    for (int s = 0; s < nslab; s++) {
        CPWAIT2();
        __syncthreads();
        // fill stage (s+3)%4 == (s-1)%4: consumed in iter s-1, safe after barrier
        if (s + 3 < nslab) fill((s + 3) % NSTAGE, s + 3);
        else CPCOMMIT();
        uint32_t sA = uA + (s % NSTAGE) * STG_A;
        uint32_t sB = uB + (s % NSTAGE) * STG_B;
        #pragma unroll
        for (int ks = 0; ks < 4; ks++) {
            uint32_t a[4][4], b[8][2];
            #pragma unroll
            for (int mt = 0; mt < 4; mt++) {
                uint32_t addr = sA + SWZ((wm + mt * 16 + a_row) * 128 + (ks * 2 + a_sel) * 16);
                LDMX4(a[mt][0], a[mt][1], a[mt][2], a[mt][3], addr);
            }
            #pragma unroll
            for (int bt = 0; bt < 4; bt++) {
                uint32_t addr = sB + SWZ((wn + bt * 16 + b_row) * 128 + (ks * 2 + b_sel) * 16);
                LDMX4(b[bt*2][0], b[bt*2][1], b[bt*2+1][0], b[bt*2+1][1], addr);
            }
            #pragma unroll
            for (int mt = 0; mt < 4; mt++)
                #pragma unroll
                for (int nt = 0; nt < 8; nt++)
                    MMA16816(acc[mt][nt], a[mt], b[nt]);
        }
        // no trailing barrier: next iteration's barrier provides the hazard fence
    }

    #pragma unroll
    for (int mt = 0; mt < 4; mt++) {
        #pragma unroll
        for (int h = 0; h < 2; h++) {
            int row = bm + wm + mt * 16 + (lane >> 2) + h * 8;
            float* crow = C + (size_t)row * N + bn + wn + 2 * (lane & 3);
            const float* rrow = addR ? (R + (size_t)row * N + bn + wn + 2 * (lane & 3)) : nullptr;
            #pragma unroll
            for (int nt = 0; nt < 8; nt++) {
                float2 ov = make_float2(acc[mt][nt][h*2], acc[mt][nt][h*2+1]);
                if (addR) {
                    float2 rv = *(const float2*)(rrow + nt * 8);
                    ov.x += rv.x; ov.y += rv.y;
                }
                *(float2*)(crow + nt * 8) = ov;
            }
        }
    }
}

// ---------------- fused RMSNorm -> (optional f32) + bf16 split ---------------
__global__ void rmsnorm_split_kernel(const float* __restrict__ x, const float* __restrict__ w,
                                     float* __restrict__ outf,
                                     __nv_bfloat16* __restrict__ outb) {
    int row = blockIdx.x;
    float4 v = ((const float4*)(x + (size_t)row * Dq))[threadIdx.x];
    float ss = v.x*v.x + v.y*v.y + v.z*v.z + v.w*v.w;
    #pragma unroll
    for (int o = 16; o; o >>= 1) ss += __shfl_xor_sync(0xffffffffu, ss, o);
    __shared__ float red[8];
    int wd = threadIdx.x >> 5, ln = threadIdx.x & 31;
    if (ln == 0) red[wd] = ss;
    __syncthreads();
    float tot = red[0]+red[1]+red[2]+red[3]+red[4]+red[5]+red[6]+red[7];
    float r = rsqrtf(tot * (1.0f / Dq) + 1e-6f);
    float4 wv = ((const float4*)w)[threadIdx.x];
    float4 ov = make_float4(v.x*r*wv.x, v.y*r*wv.y, v.z*r*wv.z, v.w*r*wv.w);
    if (outf) ((float4*)(outf + (size_t)row * Dq))[threadIdx.x] = ov;
    ull hi, lo; split4(ov, hi, lo);
    ull* rb = (ull*)(outb + (size_t)row * 3072 + threadIdx.x * 4);
    rb[0] = hi;
    *(ull*)((__nv_bfloat16*)rb + 1024) = lo;
    *(ull*)((__nv_bfloat16*)rb + 2048) = hi;
}

// ---------------- fused conv+silu+l2norm for q/k ------------------------------
__global__ void conv_l2_kernel(const float* __restrict__ in, int stride,
                               const float* __restrict__ w,
                               float* __restrict__ out, float scale) {
    int vec = blockIdx.x * 8 + (threadIdx.x >> 5);   // bt*16 + h
    int lane = threadIdx.x & 31;
    int bt = vec >> 4, h = vec & 15;
    int t = bt & (Tq - 1);
    int c = h * 64 + lane * 2;
    const float* p = in + (size_t)bt * stride + c;
    float2 x0 = *(const float2*)p;
    float2 x1 = (t >= 1) ? *(const float2*)(p - stride)     : make_float2(0.f, 0.f);
    float2 x2 = (t >= 2) ? *(const float2*)(p - 2 * stride) : make_float2(0.f, 0.f);
    float2 x3 = (t >= 3) ? *(const float2*)(p - 3 * stride) : make_float2(0.f, 0.f);
    float4 w0 = ((const float4*)w)[c];
    float4 w1 = ((const float4*)w)[c + 1];
    float a0 = w0.w*x0.x + w0.z*x1.x + w0.y*x2.x + w0.x*x3.x;
    float a1 = w1.w*x0.y + w1.z*x1.y + w1.y*x2.y + w1.x*x3.y;
    a0 = siluf(a0); a1 = siluf(a1);
    float ss = a0*a0 + a1*a1;
    #pragma unroll
    for (int o = 16; o; o >>= 1) ss += __shfl_xor_sync(0xffffffffu, ss, o);
    float r = rsqrtf(ss + 1e-6f) * scale;
    *(float2*)(out + (size_t)bt * Dq + c) = make_float2(a0 * r, a1 * r);
}

// ---------------- conv+silu for v (elementwise) -------------------------------
__global__ void conv_silu_kernel(const float* __restrict__ in, int stride,
                                 const float* __restrict__ w,
                                 float* __restrict__ out, int C) {
    size_t idx = (size_t)blockIdx.x * 256 + threadIdx.x;
    if (idx >= (size_t)Mq * C) return;
    int c = (int)(idx % C);
    size_t bt = idx / C;
    int t = (int)(bt % Tq);
    const float* p = in + bt * (size_t)stride + c;
    float4 wv = ((const float4*)w)[c];
    float acc = wv.w * p[0];
    if (t >= 1) acc += wv.z * p[-(ptrdiff_t)stride];
    if (t >= 2) acc += wv.y * p[-2 * (ptrdiff_t)stride];
    if (t >= 3) acc += wv.x * p[-3 * (ptrdiff_t)stride];
    out[idx] = siluf(acc);
}

__global__ void ba_kernel(const float* __restrict__ h, const float* __restrict__ b_w,
                          const float* __restrict__ a_w, const float* __restrict__ A_log,
                          const float* __restrict__ dt_bias,
                          float* __restrict__ beta, float* __restrict__ dec) {
    int row = blockIdx.x * 4 + (threadIdx.x >> 5);
    int lane = threadIdx.x & 31;
    int c = lane & 15;
    const float* W = (lane < 16) ? b_w : a_w;
    const float* hr = h + (size_t)row * Dq;
    float a0 = 0.f, a1 = 0.f, a2 = 0.f, a3 = 0.f;
    for (int kk = 0; kk < Dq; kk += 4) {
        a0 += hr[kk+0] * W[(kk+0)*Hq + c];
        a1 += hr[kk+1] * W[(kk+1)*Hq + c];
        a2 += hr[kk+2] * W[(kk+2)*Hq + c];
        a3 += hr[kk+3] * W[(kk+3)*Hq + c];
    }
    float acc = (a0 + a1) + (a2 + a3);
    if (lane < 16) {
        beta[(size_t)row * Hq + c] = 1.0f / (1.0f + __expf(-acc));
    } else {
        float xv = acc + dt_bias[c];
        float sp = fmaxf(xv, 0.f) + log1pf(__expf(-fabsf(xv)));
        dec[(size_t)row * Hq + c] = __expf(-__expf(A_log[c]) * sp);
    }
}

// ---------------- fused gated RMSNorm -> bf16 split ---------------------------
__global__ void gated_split_kernel(const float* __restrict__ o, const float* __restrict__ w,
                                   const float* __restrict__ gate, int gstride,
                                   __nv_bfloat16* __restrict__ outb) {
    int vec = blockIdx.x * 8 + (threadIdx.x >> 5);
    int lane = threadIdx.x & 31;
    int m = vec >> 4, hh = vec & 15;
    const float4* op = (const float4*)(o + (size_t)vec * DVq);
    const float4* gp = (const float4*)(gate + (size_t)m * gstride + hh * DVq);
    float4 v = op[lane];
    float ss = v.x*v.x + v.y*v.y + v.z*v.z + v.w*v.w;
    #pragma unroll
    for (int off = 16; off; off >>= 1) ss += __shfl_xor_sync(0xffffffffu, ss, off);
    float r = rsqrtf(ss * (1.0f / DVq) + 1e-6f);
    float4 wv = ((const float4*)w)[lane];
    float4 g = gp[lane];
    float4 ov = make_float4(v.x*r*wv.x*siluf(g.x), v.y*r*wv.y*siluf(g.y),
                            v.z*r*wv.z*siluf(g.z), v.w*r*wv.w*siluf(g.w));
    ull hi, lo; split4(ov, hi, lo);
    __nv_bfloat16* rb = outb + (size_t)m * 6144 + hh * DVq + lane * 4;
    *(ull*)rb = hi;
    *(ull*)(rb + 2048) = lo;
    *(ull*)(rb + 4096) = hi;
}

// ---------------- gated delta-rule scan v3 ------------------------------------
// 128 CTAs = (b,h,quarter). 128 thr: colL=tid>>2 (32 cols), sub=tid&3 (16 rows).
// Single reduction phase per step: ks=k·S, qs=q·S, qk=q·k on OLD S, then
// vp=d*ks; u=β(v−vp); ot=d*qs+qk*u; S=d*S+k⊗u.
// ring slot (floats): k chunks at sub*20; q at 80+sub*20; v(32) at 160; d 192; β 193.
#define RSTRIDE 196
__global__ void __launch_bounds__(128)
scan_kernel(const float* __restrict__ q, const float* __restrict__ k,
            const float* __restrict__ v, const float* __restrict__ dec,
            const float* __restrict__ bt, float* __restrict__ o) {
    __shared__ alignas(16) float ring[16 * RSTRIDE];
    int quarter = blockIdx.x & 3;
    int bh = blockIdx.x >> 2;
    int b = bh >> 4, h = bh & 15;
    int tid = threadIdx.x;
    int colL = tid >> 2, sub = tid & 3;
    int col = quarter * 32 + colL;

    size_t rowBase = (size_t)b * Tq;
    const float* kb = k + rowBase * Dq + h * DKq;
    const float* qb = q + rowBase * Dq + h * DKq;
    const float* vb = v + rowBase * VDq + h * DVq + quarter * 32;
    const float* db = dec + rowBase * Hq + h;
    const float* bb = bt + rowBase * Hq + h;
    float* ob = o + rowBase * VDq + h * DVq + col;

    uint32_t ringU = smem_u32(ring);

    auto fill = [&](int hf, int blk) {
        #pragma unroll
        for (int rep = 0; rep < 3; rep++) {
            int idx = tid + rep * 128;
            if (idx < 336) {
                int sid = idx / 42, slot = idx % 42;
                int t = blk * 8 + sid;
                uint32_t sb = ringU + ((hf * 8 + sid) * RSTRIDE) * 4;
                if (slot < 16) {
                    int ch = slot >> 2, i = slot & 3;
                    CP16(sb + (ch * 20 + i * 4) * 4,      kb + (size_t)t * Dq + ch * 16 + i * 4);
                } else if (slot < 32) {
                    int s2 = slot - 16, ch = s2 >> 2, i = s2 & 3;
                    CP16(sb + (80 + ch * 20 + i * 4) * 4, qb + (size_t)t * Dq + ch * 16 + i * 4);
                } else if (slot < 40) {
                    CP16(sb + (160 + (slot - 32) * 4) * 4, vb + (size_t)t * VDq + (slot - 32) * 4);
                } else if (slot == 40) {
                    CP4(sb + 192 * 4, db + (size_t)t * Hq);
                } else {
                    CP4(sb + 193 * 4, bb + (size_t)t * Hq);
                }
            }
        }
        CPCOMMIT();
    };

    ull S[8];
    #pragma unroll
    for (int p = 0; p < 8; p++) S[p] = 0ull;

    fill(0, 0);
    fill(1, 1);

    for (int blk = 0; blk < 256; blk++) {
        CPWAIT1();
        __syncthreads();
        int hf = blk & 1;
        #pragma unroll 1
        for (int j = 0; j < 8; j++) {
            const float* st = &ring[(hf * 8 + j) * RSTRIDE];
            const ull* kp = (const ull*)(st + sub * 20);
            const ull* qp = (const ull*)(st + 80 + sub * 20);
            float vt = st[160 + colL];
            float d = st[192], bet = st[193];
            ull kr[8], qr[8];
            #pragma unroll
            for (int p = 0; p < 8; p++) { kr[p] = kp[p]; qr[p] = qp[p]; }
            // one reduction phase: ks=k·S, qs=q·S, qk=q·k (old S), 2 chains each
            ull ksa = 0ull, ksb = 0ull, qsa = 0ull, qsb = 0ull, qka = 0ull, qkb = 0ull;
            #pragma unroll
            for (int p = 0; p < 8; p += 2) {
                ksa = ffma2(kr[p],   S[p],    ksa);
                ksb = ffma2(kr[p+1], S[p+1],  ksb);
                qsa = ffma2(qr[p],   S[p],    qsa);
                qsb = ffma2(qr[p+1], S[p+1],  qsb);
                qka = ffma2(qr[p],   kr[p],   qka);
                qkb = ffma2(qr[p+1], kr[p+1], qkb);
            }
            float2 f0 = unpk(ksa), f1 = unpk(ksb);
            float2 f2 = unpk(qsa), f3 = unpk(qsb);
            float2 f4 = unpk(qka), f5 = unpk(qkb);
            float ks = (f0.x + f0.y) + (f1.x + f1.y);
            float qs = (f2.x + f2.y) + (f3.x + f3.y);
            float qk = (f4.x + f4.y) + (f5.x + f5.y);
            // concurrent 4-lane reductions (shfl latencies overlap)
            ks += __shfl_xor_sync(0xffffffffu, ks, 1);
            qs += __shfl_xor_sync(0xffffffffu, qs, 1);
            qk += __shfl_xor_sync(0xffffffffu, qk, 1);
            ks += __shfl_xor_sync(0xffffffffu, ks, 2);
            qs += __shfl_xor_sync(0xffffffffu, qs, 2);
            qk += __shfl_xor_sync(0xffffffffu, qk, 2);
            float vp = d * ks;
            float u = bet * (vt - vp);
            float ot = d * qs + qk * u;
            ull up = dup2(u), dpk = dup2(d);
            #pragma unroll
            for (int p = 0; p < 8; p++)
                S[p] = ffma2(kr[p], up, mul2(S[p], dpk));
            if (sub == 0) ob[(size_t)(blk * 8 + j) * VDq] = ot;
        }
        __syncthreads();
        if (blk + 2 < 256) fill(hf, blk + 2);
        else CPCOMMIT();
    }
}

// ---------------- host orchestration -----------------------------------------
static inline void launch_gemm(const __nv_bfloat16* A, const __nv_bfloat16* B,
                               const float* R, float* C, int N, int KK, int addR) {
    dim3 grid(N / 256, Mq / 128);
    gemm_tc<<<grid, 256, GSMEM>>>(A, B, R, C, N, KK, addR);
}

extern "C" void kernel_launch(void* const* d_in, const int* in_sizes, int n_in,
                              void* d_out, int out_size) {
    const float* hidden   = (const float*)d_in[0];
    const float* norm_w   = (const float*)d_in[1];
    const float* q_w      = (const float*)d_in[2];
    const float* k_w      = (const float*)d_in[3];
    const float* v_w      = (const float*)d_in[4];
    const float* b_w      = (const float*)d_in[5];
    const float* a_w      = (const float*)d_in[6];
    const float* A_log    = (const float*)d_in[7];
    const float* dt_bias  = (const float*)d_in[8];
    const float* conv_q_w = (const float*)d_in[9];
    const float* conv_k_w = (const float*)d_in[10];
    const float* conv_v_w = (const float*)d_in[11];
    const float* g_wm     = (const float*)d_in[12];
    const float* o_norm_w = (const float*)d_in[13];
    const float* o_w      = (const float*)d_in[14];
    const float* post_w   = (const float*)d_in[15];
    const float* gate_w   = (const float*)d_in[16];
    const float* up_w     = (const float*)d_in[17];
    const float* down_w   = (const float*)d_in[18];
    float* out = (float*)d_out;

    float *p_h, *p_qkvg, *p_q, *p_k, *p_v, *p_bt, *p_gd, *p_o, *p_x, *p_gu;
    __nv_bfloat16 *p_A, *p_Bqkvg, *p_Bo, *p_Bmlp, *p_Bdwn;
    cudaGetSymbolAddress((void**)&p_h, g_h);
    cudaGetSymbolAddress((void**)&p_qkvg, g_qkvg);
    cudaGetSymbolAddress((void**)&p_q, g_q);
    cudaGetSymbolAddress((void**)&p_k, g_k);
    cudaGetSymbolAddress((void**)&p_v, g_v);
    cudaGetSymbolAddress((void**)&p_bt, g_bt);
    cudaGetSymbolAddress((void**)&p_gd, g_gd);
    cudaGetSymbolAddress((void**)&p_o, g_o);
    cudaGetSymbolAddress((void**)&p_x, g_x);
    cudaGetSymbolAddress((void**)&p_gu, g_gu);
    cudaGetSymbolAddress((void**)&p_A, g_Aexp);
    cudaGetSymbolAddress((void**)&p_Bqkvg, g_Bqkvg);
    cudaGetSymbolAddress((void**)&p_Bo, g_Bo);
    cudaGetSymbolAddress((void**)&p_Bmlp, g_Bmlp);
    cudaGetSymbolAddress((void**)&p_Bdwn, g_Bdwn);

    cudaFuncSetAttribute(gemm_tc, cudaFuncAttributeMaxDynamicSharedMemorySize, GSMEM);

    // weight conversion (B'' = [Bh|Bh|Bl], transposed to [N][3K])
    splitT<<<dim3(32, 32), dim3(32, 8)>>>(q_w,    p_Bqkvg,                        1024, 1024);
    splitT<<<dim3(32, 32), dim3(32, 8)>>>(k_w,    p_Bqkvg + (size_t)1024 * 3072,  1024, 1024);
    splitT<<<dim3(64, 32), dim3(32, 8)>>>(v_w,    p_Bqkvg + (size_t)2048 * 3072,  1024, 2048);
    splitT<<<dim3(64, 32), dim3(32, 8)>>>(g_wm,   p_Bqkvg + (size_t)4096 * 3072,  1024, 2048);
    splitT<<<dim3(32, 64), dim3(32, 8)>>>(o_w,    p_Bo,                           2048, 1024);
    splitT<<<dim3(86, 32), dim3(32, 8)>>>(gate_w, p_Bmlp,                         1024, 2752);
    splitT<<<dim3(86, 32), dim3(32, 8)>>>(up_w,   p_Bmlp + (size_t)2752 * 3072,   1024, 2752);
    cudaMemsetAsync(p_Bmlp + (size_t)5504 * 3072, 0, (size_t)128 * 3072 * sizeof(__nv_bfloat16));
    splitT<<<dim3(32, 86), dim3(32, 8)>>>(down_w, p_Bdwn,                         2752, 1024);

    // 1) pre-norm (fp32 for ba_kernel + bf16 split for GEMM)
    rmsnorm_split_kernel<<<Mq, 256>>>(hidden, norm_w, p_h, p_A);
    ba_kernel<<<Mq / 4, 128>>>(p_h, b_w, a_w, A_log, dt_bias, p_bt, p_gd);

    // 2) fused q|k|v|gate projection (N=6144, KK=3072)
    launch_gemm(p_A, p_Bqkvg, nullptr, p_qkvg, 6144, 3072, 0);

    // 3) conv+silu(+l2norm for q/k; q pre-scaled by dk^-0.5)
    conv_l2_kernel<<<(Mq * Hq) / 8, 256>>>(p_qkvg,        6144, conv_q_w, p_q, 0.125f);
    conv_l2_kernel<<<(Mq * Hq) / 8, 256>>>(p_qkvg + 1024, 6144, conv_k_w, p_k, 1.0f);
    conv_silu_kernel<<<(int)(((size_t)Mq * 2048 + 255) / 256), 256>>>(p_qkvg + 2048, 6144, conv_v_w, p_v, 2048);

    // 4) scan (128 CTAs, quarter-DV each)
    scan_kernel<<<Bq * Hq * 4, 128>>>(p_q, p_k, p_v, p_gd, p_bt, p_o);

    // 5) gated per-head RMSNorm -> bf16 split
    gated_split_kernel<<<(Mq * Hq) / 8, 256>>>(p_o, o_norm_w, p_qkvg + 4096, 6144, p_A);

    // 6) output projection + residual
    launch_gemm(p_A, p_Bo, hidden, p_x, 1024, 6144, 1);

    // 7) post norm -> bf16 split only
    rmsnorm_split_kernel<<<Mq, 256>>>(p_x, post_w, nullptr, p_A);

    // 8) MLP
    launch_gemm(p_A, p_Bmlp, nullptr, p_gu, FFp, 3072, 0);
    act_split<<<(int)(((size_t)Mq * FFq + 255) / 256), 256>>>(p_gu, p_A);
    launch_gemm(p_A, p_Bdwn, p_x, out, 1024, 8256, 1);
}